// round 9
// baseline (speedup 1.0000x reference)
#include <cuda_runtime.h>
#include <cuda_bf16.h>
#include <math.h>
#include <stdint.h>

#define Bsz   2
#define Lsz   2048
#define DM    768
#define DI    1536
#define NST   16
#define DTR   48
#define XDBLW 80          // DTR + 2*NST
#define MROWS (Bsz*Lsz)   // 4096
#define NC    16          // scan chunks
#define CLEN  (Lsz/NC)    // 128
#define KDT   64          // padded K for dt GEMM

typedef __nv_bfloat16 bf16;

// ---------------- scratch (device globals; no allocs allowed) ----------------
__device__ bf16  g_xz  [MROWS * 2 * DI];       // in_proj output: u_raw | z (bf16)
__device__ bf16  g_ubf [MROWS * DI];           // post conv+silu (bf16)
__device__ float g_xdbl[MROWS * XDBLW];        // dtl | B | C (fp32, scan B/C)
__device__ float g_xpp [4 * MROWS * XDBLW];    // x_proj split-K partials
__device__ bf16  g_dtbf[MROWS * DI];           // softplus(dt) (bf16)
__device__ bf16  g_ybf [MROWS * DI];           // gated scan output (bf16)
__device__ float g_opp [2 * MROWS * DM];       // out_proj split-K partials
__device__ float g_cE  [Bsz * NC * DI * NST];
__device__ float g_cH  [Bsz * NC * DI * NST];
__device__ float g_h0  [Bsz * NC * DI * NST];
// bf16 mirrors for tensor-core GEMM operands
__device__ bf16 g_xbf   [MROWS * DM];          // x
__device__ bf16 g_xdblbf[MROWS * XDBLW];       // xdbl
__device__ bf16 g_wip   [2 * DI * DM];         // in_proj_w
__device__ bf16 g_wxp   [XDBLW * DI];          // x_proj_w
__device__ bf16 g_wdt   [DI * KDT];            // dt_proj_w zero-padded 48->64
__device__ bf16 g_wop   [DM * DI];             // out_proj_w

// ---------------- helpers ----------------------------------------------------
__device__ __forceinline__ void mma_bf16(float* c, const uint32_t* a, const uint32_t* b) {
    asm volatile(
        "mma.sync.aligned.m16n8k16.row.col.f32.bf16.bf16.f32 "
        "{%0,%1,%2,%3}, {%4,%5,%6,%7}, {%8,%9}, {%0,%1,%2,%3};\n"
        : "+f"(c[0]), "+f"(c[1]), "+f"(c[2]), "+f"(c[3])
        : "r"(a[0]), "r"(a[1]), "r"(a[2]), "r"(a[3]), "r"(b[0]), "r"(b[1]));
}

__device__ __forceinline__ void ldsm4(uint32_t* r, uint32_t addr) {
    asm volatile("ldmatrix.sync.aligned.m8n8.x4.shared.b16 {%0,%1,%2,%3}, [%4];"
                 : "=r"(r[0]), "=r"(r[1]), "=r"(r[2]), "=r"(r[3]) : "r"(addr));
}

__device__ __forceinline__ float fsilu(float x) {
    return x * __fdividef(1.f, 1.f + __expf(-x));
}

__device__ __forceinline__ void cp16u(uint32_t sdst, const void* gsrc, bool pred) {
    int sz = pred ? 16 : 0;                       // src-size 0 -> zero-fill
    asm volatile("cp.async.cg.shared.global [%0], [%1], 16, %2;\n"
                 :: "r"(sdst), "l"(gsrc), "r"(sz));
}
__device__ __forceinline__ void cp_commit() { asm volatile("cp.async.commit_group;\n"); }
template<int N_>
__device__ __forceinline__ void cp_wait() { asm volatile("cp.async.wait_group %0;\n" :: "n"(N_)); }

// ---------------- fp32 -> bf16 conversion ------------------------------------
__global__ void f2bf_kernel(const float* __restrict__ src, bf16* __restrict__ dst, int n2) {
    int i = blockIdx.x * blockDim.x + threadIdx.x;
    if (i >= n2) return;
    float2 v = ((const float2*)src)[i];
    ((__nv_bfloat162*)dst)[i] = __float22bfloat162_rn(v);
}

__global__ void dtw_pad_kernel(const float* __restrict__ src, bf16* __restrict__ dst) {
    int i = blockIdx.x * blockDim.x + threadIdx.x;   // over DI*KDT
    if (i >= DI * KDT) return;
    int r = i >> 6, c = i & 63;
    dst[i] = __float2bfloat16(c < DTR ? src[r * DTR + c] : 0.f);
}

// ---------------- pipelined bf16 HMMA GEMM (ldmatrix + 3-stage) ---------------
// C[M,N] = A[M,K(lda)] * W[N,K(ldw)]^T, bf16 in, fp32 accum.
// CTA tile 128x128, BK=32, NSTG-stage cp.async ring, ldmatrix fragment loads.
// OBF==1: bf16 out; SPLITK via blockIdx.z (fp32 partials); EPI==1: softplus+bias.
#define SPB   40                 // smem row pitch in bf16 (32 data + 8 pad)
#define NSTG  3
#define ASTG  (128 * SPB * 2)    // 10240 bytes per stage per array
#define GSMEM (2 * NSTG * ASTG)  // 61440 bytes total

template<int EPI, int SPLITK, int OBF>
__global__ __launch_bounds__(256)
void gemm_bf16_kernel(const bf16* __restrict__ A, int lda,
                      const bf16* __restrict__ W, int ldw,
                      const float* __restrict__ bias,
                      void* __restrict__ Cv,
                      int M, int N, int K) {
    extern __shared__ char dsm[];
    const uint32_t smemu = (uint32_t)__cvta_generic_to_shared(dsm);
    const int tx   = threadIdx.x;
    const int lane = tx & 31;
    const int wid  = tx >> 5;
    const int warp_m = wid & 3;
    const int warp_n = wid >> 2;
    const int brow = blockIdx.y * 128;
    const int bcol = blockIdx.x * 128;
    const int q = lane & 3;
    const int g = lane >> 2;

    const int kn = K / SPLITK;
    const int kBegin = blockIdx.z * kn;
    const int KT = kn / 32;

    // staging chunk assignments: 512 x 16B chunks per array; 2 per thread
    const int cA0 = tx, cA1 = tx + 256;
    const int rA0 = cA0 >> 2, eA0 = (cA0 & 3) << 3;
    const int rA1 = cA1 >> 2, eA1 = (cA1 & 3) << 3;

    // ldmatrix per-lane byte offsets (kk=0), within a stage buffer
    // A (i=0,1): rows warp_m*32+i*16+(lane&15), col-half (lane>>4)*8
    uint32_t offA[2];
#pragma unroll
    for (int i = 0; i < 2; i++)
        offA[i] = (uint32_t)(((warp_m * 32 + i * 16 + (lane & 15)) * SPB
                              + ((lane >> 4) << 3)) * 2);
    // B (jj=0..3): rows warp_n*64+jj*16+(lane&7)+((lane>=16)?8:0), col ((lane>>3)&1)*8
    uint32_t offB[4];
#pragma unroll
    for (int jj = 0; jj < 4; jj++)
        offB[jj] = (uint32_t)(((warp_n * 64 + jj * 16 + (lane & 7) + ((lane >> 4) << 3)) * SPB
                               + (((lane >> 3) & 1) << 3)) * 2);

    float acc[2][8][4];
#pragma unroll
    for (int i = 0; i < 2; i++)
#pragma unroll
        for (int j = 0; j < 8; j++)
#pragma unroll
            for (int v = 0; v < 4; v++) acc[i][j][v] = 0.f;

    auto stage = [&](int kt) {
        int st = kt % NSTG;
        uint32_t ab = smemu + st * ASTG;
        uint32_t bb = smemu + NSTG * ASTG + st * ASTG;
        int k0 = kBegin + kt * 32;
        cp16u(ab + (uint32_t)((rA0 * SPB + eA0) * 2),
              A + (size_t)(brow + rA0) * lda + k0 + eA0, true);
        cp16u(ab + (uint32_t)((rA1 * SPB + eA1) * 2),
              A + (size_t)(brow + rA1) * lda + k0 + eA1, true);
        cp16u(bb + (uint32_t)((rA0 * SPB + eA0) * 2),
              W + (size_t)(bcol + rA0) * ldw + k0 + eA0, (bcol + rA0) < N);
        cp16u(bb + (uint32_t)((rA1 * SPB + eA1) * 2),
              W + (size_t)(bcol + rA1) * ldw + k0 + eA1, (bcol + rA1) < N);
        cp_commit();
    };

#pragma unroll
    for (int s = 0; s < NSTG; s++) {
        if (s < KT) stage(s); else cp_commit();
    }

    for (int kt = 0; kt < KT; kt++) {
        cp_wait<NSTG - 1>();
        __syncthreads();
        const int st = kt % NSTG;
        const uint32_t ab = smemu + st * ASTG;
        const uint32_t bb = smemu + NSTG * ASTG + st * ASTG;
#pragma unroll
        for (int kk = 0; kk < 32; kk += 16) {
            uint32_t af[2][4], bfr[4][4];
            ldsm4(af[0], ab + offA[0] + kk * 2);
            ldsm4(af[1], ab + offA[1] + kk * 2);
#pragma unroll
            for (int jj = 0; jj < 4; jj++)
                ldsm4(bfr[jj], bb + offB[jj] + kk * 2);
#pragma unroll
            for (int i = 0; i < 2; i++)
#pragma unroll
                for (int j = 0; j < 8; j++) {
                    const uint32_t* bp = &bfr[j >> 1][(j & 1) << 1];
                    mma_bf16(acc[i][j], af[i], bp);
                }
        }
        __syncthreads();
        if (kt + NSTG < KT) stage(kt + NSTG); else cp_commit();
    }

    // epilogue
    float* Cf = (float*)Cv + (size_t)blockIdx.z * M * N;
    bf16*  Cb = (bf16*)Cv;
#pragma unroll
    for (int i = 0; i < 2; i++) {
#pragma unroll
        for (int j = 0; j < 8; j++) {
            int r0w = brow + warp_m * 32 + i * 16 + g;
            int c0w = bcol + warp_n * 64 + j * 8 + 2 * q;
            if (c0w >= N) continue;
            float v0 = acc[i][j][0], v1 = acc[i][j][1];
            float v2 = acc[i][j][2], v3 = acc[i][j][3];
            if (EPI == 1) {
                float b0 = bias[c0w], b1 = bias[c0w + 1];
                v0 += b0; v1 += b1; v2 += b0; v3 += b1;
                v0 = (v0 > 15.f) ? v0 : __logf(1.f + __expf(v0));
                v1 = (v1 > 15.f) ? v1 : __logf(1.f + __expf(v1));
                v2 = (v2 > 15.f) ? v2 : __logf(1.f + __expf(v2));
                v3 = (v3 > 15.f) ? v3 : __logf(1.f + __expf(v3));
            }
            if (OBF) {
                *(__nv_bfloat162*)(Cb + (size_t)r0w * N + c0w) =
                    __float22bfloat162_rn(make_float2(v0, v1));
                *(__nv_bfloat162*)(Cb + (size_t)(r0w + 8) * N + c0w) =
                    __float22bfloat162_rn(make_float2(v2, v3));
            } else {
                *(float2*)(Cf + (size_t)r0w * N + c0w)       = make_float2(v0, v1);
                *(float2*)(Cf + (size_t)(r0w + 8) * N + c0w) = make_float2(v2, v3);
            }
        }
    }
}

// ---------------- x_proj split-K reduce (fp32 + bf16 outputs) ----------------
__global__ void xp_reduce_kernel(const float* __restrict__ p,
                                 float* __restrict__ o,
                                 bf16* __restrict__ obf) {
    int i = blockIdx.x * blockDim.x + threadIdx.x;
    const int S = MROWS * XDBLW;
    if (i >= S) return;
    float v = (p[i] + p[i + S]) + (p[i + 2 * S] + p[i + 3 * S]);
    o[i] = v;
    obf[i] = __float2bfloat16(v);
}

// ---------------- causal depthwise conv (k=4) + bias + SiLU ------------------
__global__ void conv_silu_kernel(const bf16* __restrict__ xz,
                                 const float* __restrict__ cw,
                                 const float* __restrict__ cb,
                                 bf16* __restrict__ u) {
    int idx = blockIdx.x * blockDim.x + threadIdx.x;   // over MROWS*DI/8
    if (idx >= MROWS * DI / 8) return;
    int d8 = idx % (DI / 8);
    int l  = (idx / (DI / 8)) % Lsz;
    int b  = idx / ((DI / 8) * Lsz);
    int d  = d8 * 8;

    float acc[8];
    {
        float4 b0 = *(const float4*)(cb + d);
        float4 b1 = *(const float4*)(cb + d + 4);
        acc[0] = b0.x; acc[1] = b0.y; acc[2] = b0.z; acc[3] = b0.w;
        acc[4] = b1.x; acc[5] = b1.y; acc[6] = b1.z; acc[7] = b1.w;
    }
    float wk[8][4];
#pragma unroll
    for (int j = 0; j < 8; j++) {
        float4 w = *(const float4*)(cw + (d + j) * 4);
        wk[j][0] = w.x; wk[j][1] = w.y; wk[j][2] = w.z; wk[j][3] = w.w;
    }
#pragma unroll
    for (int k = 0; k < 4; k++) {
        int ls = l - 3 + k;
        if (ls >= 0) {
            const __nv_bfloat162* src =
                (const __nv_bfloat162*)(xz + (size_t)(b * Lsz + ls) * (2 * DI) + d);
#pragma unroll
            for (int p = 0; p < 4; p++) {
                float2 v = __bfloat1622float2(src[p]);
                acc[2 * p]     = fmaf(wk[2 * p][k],     v.x, acc[2 * p]);
                acc[2 * p + 1] = fmaf(wk[2 * p + 1][k], v.y, acc[2 * p + 1]);
            }
        }
    }
    __nv_bfloat162 out4[4];
#pragma unroll
    for (int p = 0; p < 4; p++)
        out4[p] = __float22bfloat162_rn(make_float2(fsilu(acc[2 * p]), fsilu(acc[2 * p + 1])));
    *(uint4*)(u + (size_t)(b * Lsz + l) * DI + d) = *(uint4*)out4;
}

// ---------------- scan: shared pieces ----------------------------------------
__device__ __forceinline__ void compute_e(float e[NST], float dtv,
                                          const float A[NST], bool fast) {
    if (fast) {
        float p  = __expf(-dtv);
        float p2 = p * p, p4 = p2 * p2, p8 = p4 * p4;
        e[0]  = p;        e[1]  = p2;       e[2]  = p2 * p;   e[3]  = p4;
        e[4]  = p4 * p;   e[5]  = p4 * p2;  e[6]  = p4 * e[2];e[7]  = p8;
        e[8]  = p8 * p;   e[9]  = p8 * p2;  e[10] = p8 * e[2];e[11] = p8 * p4;
        e[12] = p8 * e[4];e[13] = p8 * e[5];e[14] = p8 * e[6];e[15] = p8 * p8;
    } else {
#pragma unroll
        for (int n = 0; n < NST; n++) e[n] = __expf(dtv * A[n]);
    }
}

__device__ __forceinline__ bool load_A(float A[NST], const float* __restrict__ A_log, int d) {
    bool fast = true;
#pragma unroll
    for (int n = 0; n < NST; n++) {
        A[n] = -expf(A_log[d * NST + n]);
        fast = fast && (fabsf(A[n] + (float)(n + 1)) <= 1e-3f * (float)(n + 1));
    }
    return fast;
}

// ---------------- scan pass 1 --------------------------------------------------
__global__ __launch_bounds__(128)
void scan_pass1_kernel(const bf16* __restrict__ dt,
                       const bf16* __restrict__ u,
                       const float* __restrict__ xdbl,
                       const float* __restrict__ A_log,
                       float* __restrict__ cE,
                       float* __restrict__ cH) {
    __shared__ float sBC[CLEN * 32];
    const int d = blockIdx.x * 128 + threadIdx.x;
    const int c = blockIdx.y;
    const int b = blockIdx.z;
    const int row0 = b * Lsz + c * CLEN;

    for (int i = threadIdx.x; i < CLEN * 32; i += 128) {
        int t = i >> 5, j = i & 31;
        sBC[i] = xdbl[(size_t)(row0 + t) * XDBLW + DTR + j];
    }
    __syncthreads();

    float A[NST];
    bool fast = load_A(A, A_log, d);
    float h[NST], E[NST];
#pragma unroll
    for (int n = 0; n < NST; n++) { h[n] = 0.f; E[n] = 1.f; }

#pragma unroll 2
    for (int t = 0; t < CLEN; t++) {
        const int row = row0 + t;
        float dtv = __bfloat162float(dt[(size_t)row * DI + d]);
        float uv  = __bfloat162float(u [(size_t)row * DI + d]);
        float e[NST];
        compute_e(e, dtv, A, fast);
        float dtu = dtv * uv;
        const float* B = &sBC[t * 32];
#pragma unroll
        for (int n = 0; n < NST; n++) {
            h[n] = fmaf(h[n], e[n], dtu * B[n]);
            E[n] *= e[n];
        }
    }
    size_t base = ((size_t)(b * NC + c) * DI + d) * NST;
#pragma unroll
    for (int n = 0; n < NST; n++) { cE[base + n] = E[n]; cH[base + n] = h[n]; }
}

// ---------------- scan combine -------------------------------------------------
__global__ void scan_combine_kernel(const float* __restrict__ cE,
                                    const float* __restrict__ cH,
                                    float* __restrict__ h0out) {
    int idx = blockIdx.x * blockDim.x + threadIdx.x;
    if (idx >= Bsz * DI * NST) return;
    int b   = idx / (DI * NST);
    int rem = idx % (DI * NST);
    float h0 = 0.f;
#pragma unroll
    for (int c = 0; c < NC; c++) {
        size_t off = (size_t)(b * NC + c) * DI * NST + rem;
        h0out[off] = h0;
        h0 = fmaf(cE[off], h0, cH[off]);
    }
}

// ---------------- scan pass 2 (emits bf16 gated y) -----------------------------
__global__ __launch_bounds__(128)
void scan_pass2_kernel(const bf16* __restrict__ dt,
                       const bf16* __restrict__ u,
                       const float* __restrict__ xdbl,
                       const bf16* __restrict__ xz,
                       const float* __restrict__ A_log,
                       const float* __restrict__ Dv,
                       const float* __restrict__ h0in,
                       bf16* __restrict__ ybf) {
    __shared__ float sBC[CLEN * 32];
    const int d = blockIdx.x * 128 + threadIdx.x;
    const int c = blockIdx.y;
    const int b = blockIdx.z;
    const int row0 = b * Lsz + c * CLEN;

    for (int i = threadIdx.x; i < CLEN * 32; i += 128) {
        int t = i >> 5, j = i & 31;
        sBC[i] = xdbl[(size_t)(row0 + t) * XDBLW + DTR + j];
    }
    __syncthreads();

    float A[NST];
    bool fast = load_A(A, A_log, d);
    float h[NST];
    size_t hbase = ((size_t)(b * NC + c) * DI + d) * NST;
#pragma unroll
    for (int n = 0; n < NST; n++) h[n] = h0in[hbase + n];
    const float Dd = Dv[d];

#pragma unroll 2
    for (int t = 0; t < CLEN; t++) {
        const int row = row0 + t;
        float dtv = __bfloat162float(dt[(size_t)row * DI + d]);
        float uv  = __bfloat162float(u [(size_t)row * DI + d]);
        float zv  = __bfloat162float(xz[(size_t)row * (2 * DI) + DI + d]);
        float e[NST];
        compute_e(e, dtv, A, fast);
        float dtu = dtv * uv;
        const float* B = &sBC[t * 32];
        const float* C = &sBC[t * 32 + 16];
        float acc = 0.f;
#pragma unroll
        for (int n = 0; n < NST; n++) {
            h[n] = fmaf(h[n], e[n], dtu * B[n]);
            acc  = fmaf(h[n], C[n], acc);
        }
        float yv = fmaf(Dd, uv, acc);
        ybf[(size_t)row * DI + d] = __float2bfloat16(yv * fsilu(zv));
    }
}

// ---------------- out_proj partial sum + residual + LayerNorm ------------------
__global__ void ln_kernel(const float* __restrict__ pre,    // 2 partials stacked
                          const float* __restrict__ resid,
                          const float* __restrict__ w,
                          const float* __restrict__ bb,
                          float* __restrict__ out) {
    const int row = blockIdx.x;
    const int tid = threadIdx.x;
    __shared__ float vbuf[DM];
    __shared__ float ws[8], w2s[8];
    __shared__ float s_mu, s_inv;
    const size_t S = (size_t)MROWS * DM;
    float s = 0.f, s2 = 0.f;
    for (int i = tid; i < DM; i += blockDim.x) {
        size_t o = (size_t)row * DM + i;
        float v = pre[o] + pre[o + S] + resid[o];
        vbuf[i] = v;
        s += v; s2 += v * v;
    }
#pragma unroll
    for (int o = 16; o; o >>= 1) {
        s  += __shfl_xor_sync(0xffffffffu, s,  o);
        s2 += __shfl_xor_sync(0xffffffffu, s2, o);
    }
    int wid = tid >> 5, lane = tid & 31;
    if (lane == 0) { ws[wid] = s; w2s[wid] = s2; }
    __syncthreads();
    if (tid == 0) {
        float S1 = 0.f, S2 = 0.f;
        for (int i = 0; i < 8; i++) { S1 += ws[i]; S2 += w2s[i]; }
        float mu  = S1 / (float)DM;
        float var = S2 / (float)DM - mu * mu;
        s_mu = mu;
        s_inv = rsqrtf(var + 1e-5f);
    }
    __syncthreads();
    float mu = s_mu, inv = s_inv;
    for (int i = tid; i < DM; i += blockDim.x)
        out[(size_t)row * DM + i] = (vbuf[i] - mu) * inv * w[i] + bb[i];
}

// ---------------- launch ----------------------------------------------------
static float* sym_ptr(const void* symbol) {
    void* p = nullptr;
    cudaGetSymbolAddress(&p, symbol);
    return (float*)p;
}
static bf16* sym_ptr_bf(const void* symbol) {
    void* p = nullptr;
    cudaGetSymbolAddress(&p, symbol);
    return (bf16*)p;
}

extern "C" void kernel_launch(void* const* d_in, const int* in_sizes, int n_in,
                              void* d_out, int out_size) {
    const float* x         = (const float*)d_in[0];
    const float* in_proj_w = (const float*)d_in[1];
    const float* conv_w    = (const float*)d_in[2];
    const float* conv_b    = (const float*)d_in[3];
    const float* x_proj_w  = (const float*)d_in[4];
    const float* dt_proj_w = (const float*)d_in[5];
    const float* dt_proj_b = (const float*)d_in[6];
    const float* A_log     = (const float*)d_in[7];
    const float* Dv        = (const float*)d_in[8];
    const float* out_proj_w= (const float*)d_in[9];
    const float* ln_w      = (const float*)d_in[10];
    const float* ln_b      = (const float*)d_in[11];
    float* out = (float*)d_out;

    bf16*  xz    = sym_ptr_bf(g_xz);
    bf16*  ubf   = sym_ptr_bf(g_ubf);
    float* xdbl  = sym_ptr(g_xdbl);
    float* xpp   = sym_ptr(g_xpp);
    bf16*  dtbf  = sym_ptr_bf(g_dtbf);
    bf16*  ybf   = sym_ptr_bf(g_ybf);
    float* opp   = sym_ptr(g_opp);
    float* cE    = sym_ptr(g_cE);
    float* cH    = sym_ptr(g_cH);
    float* h0    = sym_ptr(g_h0);
    bf16* xbf    = sym_ptr_bf(g_xbf);
    bf16* xdblbf = sym_ptr_bf(g_xdblbf);
    bf16* wip    = sym_ptr_bf(g_wip);
    bf16* wxp    = sym_ptr_bf(g_wxp);
    bf16* wdt    = sym_ptr_bf(g_wdt);
    bf16* wop    = sym_ptr_bf(g_wop);

    const int M = MROWS;

    static int attr_done = 0;
    if (!attr_done) {
        cudaFuncSetAttribute(gemm_bf16_kernel<0, 1, 1>,
                             cudaFuncAttributeMaxDynamicSharedMemorySize, GSMEM);
        cudaFuncSetAttribute(gemm_bf16_kernel<0, 4, 0>,
                             cudaFuncAttributeMaxDynamicSharedMemorySize, GSMEM);
        cudaFuncSetAttribute(gemm_bf16_kernel<1, 1, 1>,
                             cudaFuncAttributeMaxDynamicSharedMemorySize, GSMEM);
        cudaFuncSetAttribute(gemm_bf16_kernel<0, 2, 0>,
                             cudaFuncAttributeMaxDynamicSharedMemorySize, GSMEM);
        attr_done = 1;
    }

    // 0) fp32 -> bf16 conversions (weights + input activations)
    f2bf_kernel<<<(M * DM / 2 + 255) / 256, 256>>>(x, xbf, M * DM / 2);
    f2bf_kernel<<<(2 * DI * DM / 2 + 255) / 256, 256>>>(in_proj_w, wip, 2 * DI * DM / 2);
    f2bf_kernel<<<(XDBLW * DI / 2 + 255) / 256, 256>>>(x_proj_w, wxp, XDBLW * DI / 2);
    f2bf_kernel<<<(DM * DI / 2 + 255) / 256, 256>>>(out_proj_w, wop, DM * DI / 2);
    dtw_pad_kernel<<<(DI * KDT + 255) / 256, 256>>>(dt_proj_w, wdt);

    // 1) in_proj: xz[M, 3072] = x @ in_proj_w^T  (bf16 out)
    gemm_bf16_kernel<0, 1, 1><<<dim3((2 * DI) / 128, M / 128, 1), 256, GSMEM>>>(
        xbf, DM, wip, DM, nullptr, xz, M, 2 * DI, DM);

    // 2) causal depthwise conv + SiLU -> ubf
    conv_silu_kernel<<<(M * DI / 8 + 255) / 256, 256>>>(xz, conv_w, conv_b, ubf);

    // 3) x_proj: xdbl[M, 80] = u @ x_proj_w^T (split-K = 4, fp32 partials)
    gemm_bf16_kernel<0, 4, 0><<<dim3(1, M / 128, 4), 256, GSMEM>>>(
        ubf, DI, wxp, DI, nullptr, xpp, M, XDBLW, DI);
    xp_reduce_kernel<<<(M * XDBLW + 255) / 256, 256>>>(xpp, xdbl, xdblbf);

    // 4) dt[M,1536] = softplus(dtl @ dt_proj_w^T + b)  (bf16 out; K padded 48->64)
    gemm_bf16_kernel<1, 1, 1><<<dim3(DI / 128, M / 128, 1), 256, GSMEM>>>(
        xdblbf, XDBLW, wdt, KDT, dt_proj_b, dtbf, M, DI, KDT);

    // 5) chunk-parallel selective scan + gate -> ybf
    scan_pass1_kernel<<<dim3(DI / 128, NC, Bsz), 128>>>(dtbf, ubf, xdbl, A_log, cE, cH);
    scan_combine_kernel<<<(Bsz * DI * NST + 255) / 256, 256>>>(cE, cH, h0);
    scan_pass2_kernel<<<dim3(DI / 128, NC, Bsz), 128>>>(dtbf, ubf, xdbl, xz, A_log, Dv, h0, ybf);

    // 6) out_proj: opp[z][M,768] = y @ out_proj_w^T (split-K = 2)
    gemm_bf16_kernel<0, 2, 0><<<dim3(DM / 128, M / 128, 2), 256, GSMEM>>>(
        ybf, DI, wop, DI, nullptr, opp, M, DM, DI);

    // 7) partial-sum + residual + LayerNorm -> d_out
    ln_kernel<<<M, 256>>>(opp, x, ln_w, ln_b, out);
}

// round 10
// speedup vs baseline: 1.0075x; 1.0075x over previous
#include <cuda_runtime.h>
#include <cuda_bf16.h>
#include <math.h>
#include <stdint.h>

#define Bsz   2
#define Lsz   2048
#define DM    768
#define DI    1536
#define NST   16
#define DTR   48
#define XDBLW 80          // DTR + 2*NST
#define MROWS (Bsz*Lsz)   // 4096
#define NC    16          // scan chunks
#define CLEN  (Lsz/NC)    // 128
#define KDT   64          // padded K for dt GEMM

typedef __nv_bfloat16 bf16;

// ---------------- scratch (device globals; no allocs allowed) ----------------
__device__ bf16  g_xz  [MROWS * 2 * DI];       // in_proj output: u_raw | z (bf16)
__device__ bf16  g_ubf [MROWS * DI];           // post conv+silu (bf16)
__device__ float g_xdbl[MROWS * XDBLW];        // dtl | B | C (fp32, scan B/C)
__device__ float g_xpp [4 * MROWS * XDBLW];    // x_proj split-K partials
__device__ bf16  g_dtbf[MROWS * DI];           // softplus(dt) (bf16)
__device__ bf16  g_ybf [MROWS * DI];           // gated scan output (bf16)
__device__ float g_opp [2 * MROWS * DM];       // out_proj split-K partials
__device__ float g_cE  [Bsz * NC * DI * NST];
__device__ float g_cH  [Bsz * NC * DI * NST];
__device__ float g_h0  [Bsz * NC * DI * NST];
// bf16 mirrors for tensor-core GEMM operands
__device__ bf16 g_xbf   [MROWS * DM];          // x
__device__ bf16 g_xdblbf[MROWS * XDBLW];       // xdbl
__device__ bf16 g_wip   [2 * DI * DM];         // in_proj_w
__device__ bf16 g_wxp   [XDBLW * DI];          // x_proj_w
__device__ bf16 g_wdt   [DI * KDT];            // dt_proj_w zero-padded 48->64
__device__ bf16 g_wop   [DM * DI];             // out_proj_w

// ---------------- helpers ----------------------------------------------------
__device__ __forceinline__ void mma_bf16(float* c, const uint32_t* a, const uint32_t* b) {
    asm volatile(
        "mma.sync.aligned.m16n8k16.row.col.f32.bf16.bf16.f32 "
        "{%0,%1,%2,%3}, {%4,%5,%6,%7}, {%8,%9}, {%0,%1,%2,%3};\n"
        : "+f"(c[0]), "+f"(c[1]), "+f"(c[2]), "+f"(c[3])
        : "r"(a[0]), "r"(a[1]), "r"(a[2]), "r"(a[3]), "r"(b[0]), "r"(b[1]));
}

__device__ __forceinline__ void ldsm4(uint32_t* r, uint32_t addr) {
    asm volatile("ldmatrix.sync.aligned.m8n8.x4.shared.b16 {%0,%1,%2,%3}, [%4];"
                 : "=r"(r[0]), "=r"(r[1]), "=r"(r[2]), "=r"(r[3]) : "r"(addr));
}

__device__ __forceinline__ float fsilu(float x) {
    return x * __fdividef(1.f, 1.f + __expf(-x));
}

__device__ __forceinline__ void cp16u(uint32_t sdst, const void* gsrc, bool pred) {
    int sz = pred ? 16 : 0;                       // src-size 0 -> zero-fill
    asm volatile("cp.async.cg.shared.global [%0], [%1], 16, %2;\n"
                 :: "r"(sdst), "l"(gsrc), "r"(sz));
}
__device__ __forceinline__ void cp_commit() { asm volatile("cp.async.commit_group;\n"); }
template<int N_>
__device__ __forceinline__ void cp_wait() { asm volatile("cp.async.wait_group %0;\n" :: "n"(N_)); }

// ---------------- fp32 -> bf16 conversion ------------------------------------
__global__ void f2bf_kernel(const float* __restrict__ src, bf16* __restrict__ dst, int n2) {
    int i = blockIdx.x * blockDim.x + threadIdx.x;
    if (i >= n2) return;
    float2 v = ((const float2*)src)[i];
    ((__nv_bfloat162*)dst)[i] = __float22bfloat162_rn(v);
}

__global__ void dtw_pad_kernel(const float* __restrict__ src, bf16* __restrict__ dst) {
    int i = blockIdx.x * blockDim.x + threadIdx.x;   // over DI*KDT
    if (i >= DI * KDT) return;
    int r = i >> 6, c = i & 63;
    dst[i] = __float2bfloat16(c < DTR ? src[r * DTR + c] : 0.f);
}

// ---------------- pipelined bf16 HMMA GEMM (ldmatrix + 3-stage) ---------------
// C[M,N] = A[M,K(lda)] * W[N,K(ldw)]^T, bf16 in, fp32 accum.
// CTA tile 128x128, BK=32, NSTG-stage cp.async ring, ldmatrix fragment loads.
// __launch_bounds__(256,2): cap regs at 128 so 2 CTAs co-reside per SM.
// OBF==1: bf16 out; SPLITK via blockIdx.z (fp32 partials); EPI==1: softplus+bias.
#define SPB   40                 // smem row pitch in bf16 (32 data + 8 pad)
#define NSTG  3
#define ASTG  (128 * SPB * 2)    // 10240 bytes per stage per array
#define GSMEM (2 * NSTG * ASTG)  // 61440 bytes total

template<int EPI, int SPLITK, int OBF>
__global__ __launch_bounds__(256, 2)
void gemm_bf16_kernel(const bf16* __restrict__ A, int lda,
                      const bf16* __restrict__ W, int ldw,
                      const float* __restrict__ bias,
                      void* __restrict__ Cv,
                      int M, int N, int K) {
    extern __shared__ char dsm[];
    const uint32_t smemu = (uint32_t)__cvta_generic_to_shared(dsm);
    const int tx   = threadIdx.x;
    const int lane = tx & 31;
    const int wid  = tx >> 5;
    const int warp_m = wid & 3;
    const int warp_n = wid >> 2;
    const int brow = blockIdx.y * 128;
    const int bcol = blockIdx.x * 128;
    const int q = lane & 3;
    const int g = lane >> 2;

    const int kn = K / SPLITK;
    const int kBegin = blockIdx.z * kn;
    const int KT = kn / 32;

    // staging chunk assignments: 512 x 16B chunks per array; 2 per thread
    const int cA0 = tx, cA1 = tx + 256;
    const int rA0 = cA0 >> 2, eA0 = (cA0 & 3) << 3;
    const int rA1 = cA1 >> 2, eA1 = (cA1 & 3) << 3;

    // ldmatrix per-lane byte offsets (kk=0), within a stage buffer
    uint32_t offA[2];
#pragma unroll
    for (int i = 0; i < 2; i++)
        offA[i] = (uint32_t)(((warp_m * 32 + i * 16 + (lane & 15)) * SPB
                              + ((lane >> 4) << 3)) * 2);
    uint32_t offB[4];
#pragma unroll
    for (int jj = 0; jj < 4; jj++)
        offB[jj] = (uint32_t)(((warp_n * 64 + jj * 16 + (lane & 7) + ((lane >> 4) << 3)) * SPB
                               + (((lane >> 3) & 1) << 3)) * 2);

    float acc[2][8][4];
#pragma unroll
    for (int i = 0; i < 2; i++)
#pragma unroll
        for (int j = 0; j < 8; j++)
#pragma unroll
            for (int v = 0; v < 4; v++) acc[i][j][v] = 0.f;

    auto stage = [&](int kt) {
        int st = kt % NSTG;
        uint32_t ab = smemu + st * ASTG;
        uint32_t bb = smemu + NSTG * ASTG + st * ASTG;
        int k0 = kBegin + kt * 32;
        cp16u(ab + (uint32_t)((rA0 * SPB + eA0) * 2),
              A + (size_t)(brow + rA0) * lda + k0 + eA0, true);
        cp16u(ab + (uint32_t)((rA1 * SPB + eA1) * 2),
              A + (size_t)(brow + rA1) * lda + k0 + eA1, true);
        cp16u(bb + (uint32_t)((rA0 * SPB + eA0) * 2),
              W + (size_t)(bcol + rA0) * ldw + k0 + eA0, (bcol + rA0) < N);
        cp16u(bb + (uint32_t)((rA1 * SPB + eA1) * 2),
              W + (size_t)(bcol + rA1) * ldw + k0 + eA1, (bcol + rA1) < N);
        cp_commit();
    };

#pragma unroll
    for (int s = 0; s < NSTG; s++) {
        if (s < KT) stage(s); else cp_commit();
    }

    for (int kt = 0; kt < KT; kt++) {
        cp_wait<NSTG - 1>();
        __syncthreads();
        const int st = kt % NSTG;
        const uint32_t ab = smemu + st * ASTG;
        const uint32_t bb = smemu + NSTG * ASTG + st * ASTG;
#pragma unroll
        for (int kk = 0; kk < 32; kk += 16) {
            uint32_t af[2][4], bfr[4][4];
            ldsm4(af[0], ab + offA[0] + kk * 2);
            ldsm4(af[1], ab + offA[1] + kk * 2);
#pragma unroll
            for (int jj = 0; jj < 4; jj++)
                ldsm4(bfr[jj], bb + offB[jj] + kk * 2);
#pragma unroll
            for (int i = 0; i < 2; i++)
#pragma unroll
                for (int j = 0; j < 8; j++) {
                    const uint32_t* bp = &bfr[j >> 1][(j & 1) << 1];
                    mma_bf16(acc[i][j], af[i], bp);
                }
        }
        __syncthreads();
        if (kt + NSTG < KT) stage(kt + NSTG); else cp_commit();
    }

    // epilogue
    float* Cf = (float*)Cv + (size_t)blockIdx.z * M * N;
    bf16*  Cb = (bf16*)Cv;
#pragma unroll
    for (int i = 0; i < 2; i++) {
#pragma unroll
        for (int j = 0; j < 8; j++) {
            int r0w = brow + warp_m * 32 + i * 16 + g;
            int c0w = bcol + warp_n * 64 + j * 8 + 2 * q;
            if (c0w >= N) continue;
            float v0 = acc[i][j][0], v1 = acc[i][j][1];
            float v2 = acc[i][j][2], v3 = acc[i][j][3];
            if (EPI == 1) {
                float b0 = bias[c0w], b1 = bias[c0w + 1];
                v0 += b0; v1 += b1; v2 += b0; v3 += b1;
                v0 = (v0 > 15.f) ? v0 : __logf(1.f + __expf(v0));
                v1 = (v1 > 15.f) ? v1 : __logf(1.f + __expf(v1));
                v2 = (v2 > 15.f) ? v2 : __logf(1.f + __expf(v2));
                v3 = (v3 > 15.f) ? v3 : __logf(1.f + __expf(v3));
            }
            if (OBF) {
                *(__nv_bfloat162*)(Cb + (size_t)r0w * N + c0w) =
                    __float22bfloat162_rn(make_float2(v0, v1));
                *(__nv_bfloat162*)(Cb + (size_t)(r0w + 8) * N + c0w) =
                    __float22bfloat162_rn(make_float2(v2, v3));
            } else {
                *(float2*)(Cf + (size_t)r0w * N + c0w)       = make_float2(v0, v1);
                *(float2*)(Cf + (size_t)(r0w + 8) * N + c0w) = make_float2(v2, v3);
            }
        }
    }
}

// ---------------- x_proj split-K reduce (fp32 + bf16 outputs) ----------------
__global__ void xp_reduce_kernel(const float* __restrict__ p,
                                 float* __restrict__ o,
                                 bf16* __restrict__ obf) {
    int i = blockIdx.x * blockDim.x + threadIdx.x;
    const int S = MROWS * XDBLW;
    if (i >= S) return;
    float v = (p[i] + p[i + S]) + (p[i + 2 * S] + p[i + 3 * S]);
    o[i] = v;
    obf[i] = __float2bfloat16(v);
}

// ---------------- causal depthwise conv (k=4) + bias + SiLU ------------------
__global__ void conv_silu_kernel(const bf16* __restrict__ xz,
                                 const float* __restrict__ cw,
                                 const float* __restrict__ cb,
                                 bf16* __restrict__ u) {
    int idx = blockIdx.x * blockDim.x + threadIdx.x;   // over MROWS*DI/8
    if (idx >= MROWS * DI / 8) return;
    int d8 = idx % (DI / 8);
    int l  = (idx / (DI / 8)) % Lsz;
    int b  = idx / ((DI / 8) * Lsz);
    int d  = d8 * 8;

    float acc[8];
    {
        float4 b0 = *(const float4*)(cb + d);
        float4 b1 = *(const float4*)(cb + d + 4);
        acc[0] = b0.x; acc[1] = b0.y; acc[2] = b0.z; acc[3] = b0.w;
        acc[4] = b1.x; acc[5] = b1.y; acc[6] = b1.z; acc[7] = b1.w;
    }
    float wk[8][4];
#pragma unroll
    for (int j = 0; j < 8; j++) {
        float4 w = *(const float4*)(cw + (d + j) * 4);
        wk[j][0] = w.x; wk[j][1] = w.y; wk[j][2] = w.z; wk[j][3] = w.w;
    }
#pragma unroll
    for (int k = 0; k < 4; k++) {
        int ls = l - 3 + k;
        if (ls >= 0) {
            const __nv_bfloat162* src =
                (const __nv_bfloat162*)(xz + (size_t)(b * Lsz + ls) * (2 * DI) + d);
#pragma unroll
            for (int p = 0; p < 4; p++) {
                float2 v = __bfloat1622float2(src[p]);
                acc[2 * p]     = fmaf(wk[2 * p][k],     v.x, acc[2 * p]);
                acc[2 * p + 1] = fmaf(wk[2 * p + 1][k], v.y, acc[2 * p + 1]);
            }
        }
    }
    __nv_bfloat162 out4[4];
#pragma unroll
    for (int p = 0; p < 4; p++)
        out4[p] = __float22bfloat162_rn(make_float2(fsilu(acc[2 * p]), fsilu(acc[2 * p + 1])));
    *(uint4*)(u + (size_t)(b * Lsz + l) * DI + d) = *(uint4*)out4;
}

// ---------------- scan: shared pieces ----------------------------------------
__device__ __forceinline__ void compute_e(float e[NST], float dtv,
                                          const float A[NST], bool fast) {
    if (fast) {
        float p  = __expf(-dtv);
        float p2 = p * p, p4 = p2 * p2, p8 = p4 * p4;
        e[0]  = p;        e[1]  = p2;       e[2]  = p2 * p;   e[3]  = p4;
        e[4]  = p4 * p;   e[5]  = p4 * p2;  e[6]  = p4 * e[2];e[7]  = p8;
        e[8]  = p8 * p;   e[9]  = p8 * p2;  e[10] = p8 * e[2];e[11] = p8 * p4;
        e[12] = p8 * e[4];e[13] = p8 * e[5];e[14] = p8 * e[6];e[15] = p8 * p8;
    } else {
#pragma unroll
        for (int n = 0; n < NST; n++) e[n] = __expf(dtv * A[n]);
    }
}

__device__ __forceinline__ bool load_A(float A[NST], const float* __restrict__ A_log, int d) {
    bool fast = true;
#pragma unroll
    for (int n = 0; n < NST; n++) {
        A[n] = -expf(A_log[d * NST + n]);
        fast = fast && (fabsf(A[n] + (float)(n + 1)) <= 1e-3f * (float)(n + 1));
    }
    return fast;
}

// ---------------- scan pass 1 --------------------------------------------------
__global__ __launch_bounds__(128)
void scan_pass1_kernel(const bf16* __restrict__ dt,
                       const bf16* __restrict__ u,
                       const float* __restrict__ xdbl,
                       const float* __restrict__ A_log,
                       float* __restrict__ cE,
                       float* __restrict__ cH) {
    __shared__ float sBC[CLEN * 32];
    const int d = blockIdx.x * 128 + threadIdx.x;
    const int c = blockIdx.y;
    const int b = blockIdx.z;
    const int row0 = b * Lsz + c * CLEN;

    for (int i = threadIdx.x; i < CLEN * 32; i += 128) {
        int t = i >> 5, j = i & 31;
        sBC[i] = xdbl[(size_t)(row0 + t) * XDBLW + DTR + j];
    }
    __syncthreads();

    float A[NST];
    bool fast = load_A(A, A_log, d);
    float h[NST], E[NST];
#pragma unroll
    for (int n = 0; n < NST; n++) { h[n] = 0.f; E[n] = 1.f; }

#pragma unroll 2
    for (int t = 0; t < CLEN; t++) {
        const int row = row0 + t;
        float dtv = __bfloat162float(dt[(size_t)row * DI + d]);
        float uv  = __bfloat162float(u [(size_t)row * DI + d]);
        float e[NST];
        compute_e(e, dtv, A, fast);
        float dtu = dtv * uv;
        const float* B = &sBC[t * 32];
#pragma unroll
        for (int n = 0; n < NST; n++) {
            h[n] = fmaf(h[n], e[n], dtu * B[n]);
            E[n] *= e[n];
        }
    }
    size_t base = ((size_t)(b * NC + c) * DI + d) * NST;
#pragma unroll
    for (int n = 0; n < NST; n++) { cE[base + n] = E[n]; cH[base + n] = h[n]; }
}

// ---------------- scan combine -------------------------------------------------
__global__ void scan_combine_kernel(const float* __restrict__ cE,
                                    const float* __restrict__ cH,
                                    float* __restrict__ h0out) {
    int idx = blockIdx.x * blockDim.x + threadIdx.x;
    if (idx >= Bsz * DI * NST) return;
    int b   = idx / (DI * NST);
    int rem = idx % (DI * NST);
    float h0 = 0.f;
#pragma unroll
    for (int c = 0; c < NC; c++) {
        size_t off = (size_t)(b * NC + c) * DI * NST + rem;
        h0out[off] = h0;
        h0 = fmaf(cE[off], h0, cH[off]);
    }
}

// ---------------- scan pass 2 (emits bf16 gated y) -----------------------------
__global__ __launch_bounds__(128)
void scan_pass2_kernel(const bf16* __restrict__ dt,
                       const bf16* __restrict__ u,
                       const float* __restrict__ xdbl,
                       const bf16* __restrict__ xz,
                       const float* __restrict__ A_log,
                       const float* __restrict__ Dv,
                       const float* __restrict__ h0in,
                       bf16* __restrict__ ybf) {
    __shared__ float sBC[CLEN * 32];
    const int d = blockIdx.x * 128 + threadIdx.x;
    const int c = blockIdx.y;
    const int b = blockIdx.z;
    const int row0 = b * Lsz + c * CLEN;

    for (int i = threadIdx.x; i < CLEN * 32; i += 128) {
        int t = i >> 5, j = i & 31;
        sBC[i] = xdbl[(size_t)(row0 + t) * XDBLW + DTR + j];
    }
    __syncthreads();

    float A[NST];
    bool fast = load_A(A, A_log, d);
    float h[NST];
    size_t hbase = ((size_t)(b * NC + c) * DI + d) * NST;
#pragma unroll
    for (int n = 0; n < NST; n++) h[n] = h0in[hbase + n];
    const float Dd = Dv[d];

#pragma unroll 2
    for (int t = 0; t < CLEN; t++) {
        const int row = row0 + t;
        float dtv = __bfloat162float(dt[(size_t)row * DI + d]);
        float uv  = __bfloat162float(u [(size_t)row * DI + d]);
        float zv  = __bfloat162float(xz[(size_t)row * (2 * DI) + DI + d]);
        float e[NST];
        compute_e(e, dtv, A, fast);
        float dtu = dtv * uv;
        const float* B = &sBC[t * 32];
        const float* C = &sBC[t * 32 + 16];
        float acc = 0.f;
#pragma unroll
        for (int n = 0; n < NST; n++) {
            h[n] = fmaf(h[n], e[n], dtu * B[n]);
            acc  = fmaf(h[n], C[n], acc);
        }
        float yv = fmaf(Dd, uv, acc);
        ybf[(size_t)row * DI + d] = __float2bfloat16(yv * fsilu(zv));
    }
}

// ---------------- out_proj partial sum + residual + LayerNorm ------------------
__global__ void ln_kernel(const float* __restrict__ pre,    // 2 partials stacked
                          const float* __restrict__ resid,
                          const float* __restrict__ w,
                          const float* __restrict__ bb,
                          float* __restrict__ out) {
    const int row = blockIdx.x;
    const int tid = threadIdx.x;
    __shared__ float vbuf[DM];
    __shared__ float ws[8], w2s[8];
    __shared__ float s_mu, s_inv;
    const size_t S = (size_t)MROWS * DM;
    float s = 0.f, s2 = 0.f;
    for (int i = tid; i < DM; i += blockDim.x) {
        size_t o = (size_t)row * DM + i;
        float v = pre[o] + pre[o + S] + resid[o];
        vbuf[i] = v;
        s += v; s2 += v * v;
    }
#pragma unroll
    for (int o = 16; o; o >>= 1) {
        s  += __shfl_xor_sync(0xffffffffu, s,  o);
        s2 += __shfl_xor_sync(0xffffffffu, s2, o);
    }
    int wid = tid >> 5, lane = tid & 31;
    if (lane == 0) { ws[wid] = s; w2s[wid] = s2; }
    __syncthreads();
    if (tid == 0) {
        float S1 = 0.f, S2 = 0.f;
        for (int i = 0; i < 8; i++) { S1 += ws[i]; S2 += w2s[i]; }
        float mu  = S1 / (float)DM;
        float var = S2 / (float)DM - mu * mu;
        s_mu = mu;
        s_inv = rsqrtf(var + 1e-5f);
    }
    __syncthreads();
    float mu = s_mu, inv = s_inv;
    for (int i = tid; i < DM; i += blockDim.x)
        out[(size_t)row * DM + i] = (vbuf[i] - mu) * inv * w[i] + bb[i];
}

// ---------------- launch ----------------------------------------------------
static float* sym_ptr(const void* symbol) {
    void* p = nullptr;
    cudaGetSymbolAddress(&p, symbol);
    return (float*)p;
}
static bf16* sym_ptr_bf(const void* symbol) {
    void* p = nullptr;
    cudaGetSymbolAddress(&p, symbol);
    return (bf16*)p;
}

extern "C" void kernel_launch(void* const* d_in, const int* in_sizes, int n_in,
                              void* d_out, int out_size) {
    const float* x         = (const float*)d_in[0];
    const float* in_proj_w = (const float*)d_in[1];
    const float* conv_w    = (const float*)d_in[2];
    const float* conv_b    = (const float*)d_in[3];
    const float* x_proj_w  = (const float*)d_in[4];
    const float* dt_proj_w = (const float*)d_in[5];
    const float* dt_proj_b = (const float*)d_in[6];
    const float* A_log     = (const float*)d_in[7];
    const float* Dv        = (const float*)d_in[8];
    const float* out_proj_w= (const float*)d_in[9];
    const float* ln_w      = (const float*)d_in[10];
    const float* ln_b      = (const float*)d_in[11];
    float* out = (float*)d_out;

    bf16*  xz    = sym_ptr_bf(g_xz);
    bf16*  ubf   = sym_ptr_bf(g_ubf);
    float* xdbl  = sym_ptr(g_xdbl);
    float* xpp   = sym_ptr(g_xpp);
    bf16*  dtbf  = sym_ptr_bf(g_dtbf);
    bf16*  ybf   = sym_ptr_bf(g_ybf);
    float* opp   = sym_ptr(g_opp);
    float* cE    = sym_ptr(g_cE);
    float* cH    = sym_ptr(g_cH);
    float* h0    = sym_ptr(g_h0);
    bf16* xbf    = sym_ptr_bf(g_xbf);
    bf16* xdblbf = sym_ptr_bf(g_xdblbf);
    bf16* wip    = sym_ptr_bf(g_wip);
    bf16* wxp    = sym_ptr_bf(g_wxp);
    bf16* wdt    = sym_ptr_bf(g_wdt);
    bf16* wop    = sym_ptr_bf(g_wop);

    const int M = MROWS;

    static int attr_done = 0;
    if (!attr_done) {
        cudaFuncSetAttribute(gemm_bf16_kernel<0, 1, 1>,
                             cudaFuncAttributeMaxDynamicSharedMemorySize, GSMEM);
        cudaFuncSetAttribute(gemm_bf16_kernel<0, 4, 0>,
                             cudaFuncAttributeMaxDynamicSharedMemorySize, GSMEM);
        cudaFuncSetAttribute(gemm_bf16_kernel<1, 1, 1>,
                             cudaFuncAttributeMaxDynamicSharedMemorySize, GSMEM);
        cudaFuncSetAttribute(gemm_bf16_kernel<0, 2, 0>,
                             cudaFuncAttributeMaxDynamicSharedMemorySize, GSMEM);
        attr_done = 1;
    }

    // 0a) conversions needed by in_proj (launches 1-3)
    f2bf_kernel<<<(M * DM / 2 + 255) / 256, 256>>>(x, xbf, M * DM / 2);
    f2bf_kernel<<<(2 * DI * DM / 2 + 255) / 256, 256>>>(in_proj_w, wip, 2 * DI * DM / 2);
    f2bf_kernel<<<(XDBLW * DI / 2 + 255) / 256, 256>>>(x_proj_w, wxp, XDBLW * DI / 2);

    // 1) in_proj: xz[M, 3072] = x @ in_proj_w^T  (bf16 out)  [launch #4 -> profiled]
    gemm_bf16_kernel<0, 1, 1><<<dim3((2 * DI) / 128, M / 128, 1), 256, GSMEM>>>(
        xbf, DM, wip, DM, nullptr, xz, M, 2 * DI, DM);

    // 0b) remaining conversions (independent of in_proj output)
    f2bf_kernel<<<(DM * DI / 2 + 255) / 256, 256>>>(out_proj_w, wop, DM * DI / 2);
    dtw_pad_kernel<<<(DI * KDT + 255) / 256, 256>>>(dt_proj_w, wdt);

    // 2) causal depthwise conv + SiLU -> ubf
    conv_silu_kernel<<<(M * DI / 8 + 255) / 256, 256>>>(xz, conv_w, conv_b, ubf);

    // 3) x_proj: xdbl[M, 80] = u @ x_proj_w^T (split-K = 4, fp32 partials)
    gemm_bf16_kernel<0, 4, 0><<<dim3(1, M / 128, 4), 256, GSMEM>>>(
        ubf, DI, wxp, DI, nullptr, xpp, M, XDBLW, DI);
    xp_reduce_kernel<<<(M * XDBLW + 255) / 256, 256>>>(xpp, xdbl, xdblbf);

    // 4) dt[M,1536] = softplus(dtl @ dt_proj_w^T + b)  (bf16 out; K padded 48->64)
    gemm_bf16_kernel<1, 1, 1><<<dim3(DI / 128, M / 128, 1), 256, GSMEM>>>(
        xdblbf, XDBLW, wdt, KDT, dt_proj_b, dtbf, M, DI, KDT);

    // 5) chunk-parallel selective scan + gate -> ybf
    scan_pass1_kernel<<<dim3(DI / 128, NC, Bsz), 128>>>(dtbf, ubf, xdbl, A_log, cE, cH);
    scan_combine_kernel<<<(Bsz * DI * NST + 255) / 256, 256>>>(cE, cH, h0);
    scan_pass2_kernel<<<dim3(DI / 128, NC, Bsz), 128>>>(dtbf, ubf, xdbl, xz, A_log, Dv, h0, ybf);

    // 6) out_proj: opp[z][M,768] = y @ out_proj_w^T (split-K = 2)
    gemm_bf16_kernel<0, 2, 0><<<dim3(DM / 128, M / 128, 2), 256, GSMEM>>>(
        ybf, DI, wop, DI, nullptr, opp, M, DM, DI);

    // 7) partial-sum + residual + LayerNorm -> d_out
    ln_kernel<<<M, 256>>>(opp, x, ln_w, ln_b, out);
}

// round 11
// speedup vs baseline: 1.0600x; 1.0522x over previous
#include <cuda_runtime.h>
#include <cuda_bf16.h>
#include <math.h>
#include <stdint.h>

#define Bsz   2
#define Lsz   2048
#define DM    768
#define DI    1536
#define NST   16
#define DTR   48
#define XDBLW 80          // DTR + 2*NST
#define MROWS (Bsz*Lsz)   // 4096
#define NC    16          // scan chunks
#define CLEN  (Lsz/NC)    // 128
#define KDT   64          // padded K for dt GEMM

typedef __nv_bfloat16 bf16;

// ---------------- scratch (device globals; no allocs allowed) ----------------
__device__ bf16  g_xz  [MROWS * 2 * DI];       // in_proj output: u_raw | z (bf16)
__device__ bf16  g_ubf [MROWS * DI];           // post conv+silu (bf16)
__device__ float g_xdbl[MROWS * XDBLW];        // dtl | B | C (fp32, scan B/C)
__device__ float g_xpp [4 * MROWS * XDBLW];    // x_proj split-K partials
__device__ bf16  g_dtbf[MROWS * DI];           // softplus(dt) (bf16)
__device__ bf16  g_ybf [MROWS * DI];           // gated scan output (bf16)
__device__ float g_opp [2 * MROWS * DM];       // out_proj split-K partials
__device__ float g_cE  [Bsz * NC * DI * NST];
__device__ float g_cH  [Bsz * NC * DI * NST];
__device__ float g_h0  [Bsz * NC * DI * NST];
// bf16 mirrors for tensor-core GEMM operands
__device__ bf16 g_xbf   [MROWS * DM];          // x
__device__ bf16 g_xdblbf[MROWS * XDBLW];       // xdbl
__device__ bf16 g_wip   [2 * DI * DM];         // in_proj_w
__device__ bf16 g_wxp   [XDBLW * DI];          // x_proj_w
__device__ bf16 g_wdt   [DI * KDT];            // dt_proj_w zero-padded 48->64
__device__ bf16 g_wop   [DM * DI];             // out_proj_w

// ---------------- helpers ----------------------------------------------------
__device__ __forceinline__ void mma_bf16(float* c, const uint32_t* a, const uint32_t* b) {
    asm volatile(
        "mma.sync.aligned.m16n8k16.row.col.f32.bf16.bf16.f32 "
        "{%0,%1,%2,%3}, {%4,%5,%6,%7}, {%8,%9}, {%0,%1,%2,%3};\n"
        : "+f"(c[0]), "+f"(c[1]), "+f"(c[2]), "+f"(c[3])
        : "r"(a[0]), "r"(a[1]), "r"(a[2]), "r"(a[3]), "r"(b[0]), "r"(b[1]));
}

__device__ __forceinline__ void ldsm4(uint32_t* r, uint32_t addr) {
    asm volatile("ldmatrix.sync.aligned.m8n8.x4.shared.b16 {%0,%1,%2,%3}, [%4];"
                 : "=r"(r[0]), "=r"(r[1]), "=r"(r[2]), "=r"(r[3]) : "r"(addr));
}

__device__ __forceinline__ float fsilu(float x) {
    return x * __fdividef(1.f, 1.f + __expf(-x));
}

__device__ __forceinline__ void cp16u(uint32_t sdst, const void* gsrc, bool pred) {
    int sz = pred ? 16 : 0;                       // src-size 0 -> zero-fill
    asm volatile("cp.async.cg.shared.global [%0], [%1], 16, %2;\n"
                 :: "r"(sdst), "l"(gsrc), "r"(sz));
}
__device__ __forceinline__ void cp_commit() { asm volatile("cp.async.commit_group;\n"); }
template<int N_>
__device__ __forceinline__ void cp_wait() { asm volatile("cp.async.wait_group %0;\n" :: "n"(N_)); }

// ---------------- fp32 -> bf16 conversion ------------------------------------
__global__ void f2bf_kernel(const float* __restrict__ src, bf16* __restrict__ dst, int n2) {
    int i = blockIdx.x * blockDim.x + threadIdx.x;
    if (i >= n2) return;
    float2 v = ((const float2*)src)[i];
    ((__nv_bfloat162*)dst)[i] = __float22bfloat162_rn(v);
}

__global__ void dtw_pad_kernel(const float* __restrict__ src, bf16* __restrict__ dst) {
    int i = blockIdx.x * blockDim.x + threadIdx.x;   // over DI*KDT
    if (i >= DI * KDT) return;
    int r = i >> 6, c = i & 63;
    dst[i] = __float2bfloat16(c < DTR ? src[r * DTR + c] : 0.f);
}

// ---------------- pipelined bf16 HMMA GEMM (ldmatrix, BK=64, 2-stage) ---------
// C[M,N] = A[M,K(lda)] * W[N,K(ldw)]^T, bf16 in, fp32 accum.
// CTA tile 128x128, BK=64, 2-stage cp.async double buffer (one barrier pair
// per 64 K-elements), ldmatrix fragment loads. 2 CTAs/SM.
// OBF==1: bf16 out; SPLITK via blockIdx.z (fp32 partials); EPI==1: softplus+bias.
#define SPB   72                 // smem row pitch in bf16 (64 data + 8 pad)
#define NSTG  2
#define ASTG  (128 * SPB * 2)    // 18432 bytes per stage per array
#define GSMEM (2 * NSTG * ASTG)  // 73728 bytes total

template<int EPI, int SPLITK, int OBF>
__global__ __launch_bounds__(256, 2)
void gemm_bf16_kernel(const bf16* __restrict__ A, int lda,
                      const bf16* __restrict__ W, int ldw,
                      const float* __restrict__ bias,
                      void* __restrict__ Cv,
                      int M, int N, int K) {
    extern __shared__ char dsm[];
    const uint32_t smemu = (uint32_t)__cvta_generic_to_shared(dsm);
    const int tx   = threadIdx.x;
    const int lane = tx & 31;
    const int wid  = tx >> 5;
    const int warp_m = wid & 3;
    const int warp_n = wid >> 2;
    const int brow = blockIdx.y * 128;
    const int bcol = blockIdx.x * 128;
    const int q = lane & 3;
    const int g = lane >> 2;

    const int kn = K / SPLITK;
    const int kBegin = blockIdx.z * kn;
    const int KT = kn / 64;

    // staging: 1024 x 16B chunks per array-stage; 4 per thread
    // chunk c: row = c>>3, elem-offset = (c&7)*8 (bf16)
    int rS[4], eS[4];
#pragma unroll
    for (int i = 0; i < 4; i++) {
        int c = tx + i * 256;
        rS[i] = c >> 3;
        eS[i] = (c & 7) << 3;
    }

    // ldmatrix per-lane byte offsets (kk=0) within a stage buffer
    uint32_t offA[2];
#pragma unroll
    for (int i = 0; i < 2; i++)
        offA[i] = (uint32_t)(((warp_m * 32 + i * 16 + (lane & 15)) * SPB
                              + ((lane >> 4) << 3)) * 2);
    uint32_t offB[4];
#pragma unroll
    for (int jj = 0; jj < 4; jj++)
        offB[jj] = (uint32_t)(((warp_n * 64 + jj * 16 + (lane & 7) + ((lane >> 4) << 3)) * SPB
                               + (((lane >> 3) & 1) << 3)) * 2);

    float acc[2][8][4];
#pragma unroll
    for (int i = 0; i < 2; i++)
#pragma unroll
        for (int j = 0; j < 8; j++)
#pragma unroll
            for (int v = 0; v < 4; v++) acc[i][j][v] = 0.f;

    auto stage = [&](int kt) {
        int st = kt & 1;
        uint32_t ab = smemu + st * ASTG;
        uint32_t bb = smemu + NSTG * ASTG + st * ASTG;
        int k0 = kBegin + kt * 64;
#pragma unroll
        for (int i = 0; i < 4; i++) {
            cp16u(ab + (uint32_t)((rS[i] * SPB + eS[i]) * 2),
                  A + (size_t)(brow + rS[i]) * lda + k0 + eS[i], true);
            cp16u(bb + (uint32_t)((rS[i] * SPB + eS[i]) * 2),
                  W + (size_t)(bcol + rS[i]) * ldw + k0 + eS[i], (bcol + rS[i]) < N);
        }
        cp_commit();
    };

#pragma unroll
    for (int s = 0; s < NSTG; s++) {
        if (s < KT) stage(s); else cp_commit();
    }

    for (int kt = 0; kt < KT; kt++) {
        cp_wait<NSTG - 1>();
        __syncthreads();
        const int st = kt & 1;
        const uint32_t ab = smemu + st * ASTG;
        const uint32_t bb = smemu + NSTG * ASTG + st * ASTG;
#pragma unroll
        for (int kk = 0; kk < 64; kk += 16) {
            uint32_t af[2][4], bfr[4][4];
            ldsm4(af[0], ab + offA[0] + kk * 2);
            ldsm4(af[1], ab + offA[1] + kk * 2);
#pragma unroll
            for (int jj = 0; jj < 4; jj++)
                ldsm4(bfr[jj], bb + offB[jj] + kk * 2);
#pragma unroll
            for (int i = 0; i < 2; i++)
#pragma unroll
                for (int j = 0; j < 8; j++) {
                    const uint32_t* bp = &bfr[j >> 1][(j & 1) << 1];
                    mma_bf16(acc[i][j], af[i], bp);
                }
        }
        __syncthreads();
        if (kt + NSTG < KT) stage(kt + NSTG); else cp_commit();
    }

    // epilogue
    float* Cf = (float*)Cv + (size_t)blockIdx.z * M * N;
    bf16*  Cb = (bf16*)Cv;
#pragma unroll
    for (int i = 0; i < 2; i++) {
#pragma unroll
        for (int j = 0; j < 8; j++) {
            int r0w = brow + warp_m * 32 + i * 16 + g;
            int c0w = bcol + warp_n * 64 + j * 8 + 2 * q;
            if (c0w >= N) continue;
            float v0 = acc[i][j][0], v1 = acc[i][j][1];
            float v2 = acc[i][j][2], v3 = acc[i][j][3];
            if (EPI == 1) {
                float b0 = bias[c0w], b1 = bias[c0w + 1];
                v0 += b0; v1 += b1; v2 += b0; v3 += b1;
                v0 = (v0 > 15.f) ? v0 : __logf(1.f + __expf(v0));
                v1 = (v1 > 15.f) ? v1 : __logf(1.f + __expf(v1));
                v2 = (v2 > 15.f) ? v2 : __logf(1.f + __expf(v2));
                v3 = (v3 > 15.f) ? v3 : __logf(1.f + __expf(v3));
            }
            if (OBF) {
                *(__nv_bfloat162*)(Cb + (size_t)r0w * N + c0w) =
                    __float22bfloat162_rn(make_float2(v0, v1));
                *(__nv_bfloat162*)(Cb + (size_t)(r0w + 8) * N + c0w) =
                    __float22bfloat162_rn(make_float2(v2, v3));
            } else {
                *(float2*)(Cf + (size_t)r0w * N + c0w)       = make_float2(v0, v1);
                *(float2*)(Cf + (size_t)(r0w + 8) * N + c0w) = make_float2(v2, v3);
            }
        }
    }
}

// ---------------- x_proj split-K reduce (fp32 + bf16 outputs) ----------------
__global__ void xp_reduce_kernel(const float* __restrict__ p,
                                 float* __restrict__ o,
                                 bf16* __restrict__ obf) {
    int i = blockIdx.x * blockDim.x + threadIdx.x;
    const int S = MROWS * XDBLW;
    if (i >= S) return;
    float v = (p[i] + p[i + S]) + (p[i + 2 * S] + p[i + 3 * S]);
    o[i] = v;
    obf[i] = __float2bfloat16(v);
}

// ---------------- causal depthwise conv (k=4) + bias + SiLU ------------------
__global__ void conv_silu_kernel(const bf16* __restrict__ xz,
                                 const float* __restrict__ cw,
                                 const float* __restrict__ cb,
                                 bf16* __restrict__ u) {
    int idx = blockIdx.x * blockDim.x + threadIdx.x;   // over MROWS*DI/8
    if (idx >= MROWS * DI / 8) return;
    int d8 = idx % (DI / 8);
    int l  = (idx / (DI / 8)) % Lsz;
    int b  = idx / ((DI / 8) * Lsz);
    int d  = d8 * 8;

    float acc[8];
    {
        float4 b0 = *(const float4*)(cb + d);
        float4 b1 = *(const float4*)(cb + d + 4);
        acc[0] = b0.x; acc[1] = b0.y; acc[2] = b0.z; acc[3] = b0.w;
        acc[4] = b1.x; acc[5] = b1.y; acc[6] = b1.z; acc[7] = b1.w;
    }
    float wk[8][4];
#pragma unroll
    for (int j = 0; j < 8; j++) {
        float4 w = *(const float4*)(cw + (d + j) * 4);
        wk[j][0] = w.x; wk[j][1] = w.y; wk[j][2] = w.z; wk[j][3] = w.w;
    }
#pragma unroll
    for (int k = 0; k < 4; k++) {
        int ls = l - 3 + k;
        if (ls >= 0) {
            const __nv_bfloat162* src =
                (const __nv_bfloat162*)(xz + (size_t)(b * Lsz + ls) * (2 * DI) + d);
#pragma unroll
            for (int p = 0; p < 4; p++) {
                float2 v = __bfloat1622float2(src[p]);
                acc[2 * p]     = fmaf(wk[2 * p][k],     v.x, acc[2 * p]);
                acc[2 * p + 1] = fmaf(wk[2 * p + 1][k], v.y, acc[2 * p + 1]);
            }
        }
    }
    __nv_bfloat162 out4[4];
#pragma unroll
    for (int p = 0; p < 4; p++)
        out4[p] = __float22bfloat162_rn(make_float2(fsilu(acc[2 * p]), fsilu(acc[2 * p + 1])));
    *(uint4*)(u + (size_t)(b * Lsz + l) * DI + d) = *(uint4*)out4;
}

// ---------------- scan: shared pieces ----------------------------------------
__device__ __forceinline__ void compute_e(float e[NST], float dtv,
                                          const float A[NST], bool fast) {
    if (fast) {
        float p  = __expf(-dtv);
        float p2 = p * p, p4 = p2 * p2, p8 = p4 * p4;
        e[0]  = p;        e[1]  = p2;       e[2]  = p2 * p;   e[3]  = p4;
        e[4]  = p4 * p;   e[5]  = p4 * p2;  e[6]  = p4 * e[2];e[7]  = p8;
        e[8]  = p8 * p;   e[9]  = p8 * p2;  e[10] = p8 * e[2];e[11] = p8 * p4;
        e[12] = p8 * e[4];e[13] = p8 * e[5];e[14] = p8 * e[6];e[15] = p8 * p8;
    } else {
#pragma unroll
        for (int n = 0; n < NST; n++) e[n] = __expf(dtv * A[n]);
    }
}

__device__ __forceinline__ bool load_A(float A[NST], const float* __restrict__ A_log, int d) {
    bool fast = true;
#pragma unroll
    for (int n = 0; n < NST; n++) {
        A[n] = -expf(A_log[d * NST + n]);
        fast = fast && (fabsf(A[n] + (float)(n + 1)) <= 1e-3f * (float)(n + 1));
    }
    return fast;
}

// ---------------- scan pass 1 --------------------------------------------------
// E[n] = prod_t exp(dt_t*A[n]) == exp(A[n] * sum_t dt_t): accumulate one scalar.
__global__ __launch_bounds__(128)
void scan_pass1_kernel(const bf16* __restrict__ dt,
                       const bf16* __restrict__ u,
                       const float* __restrict__ xdbl,
                       const float* __restrict__ A_log,
                       float* __restrict__ cE,
                       float* __restrict__ cH) {
    __shared__ float sBC[CLEN * 32];
    const int d = blockIdx.x * 128 + threadIdx.x;
    const int c = blockIdx.y;
    const int b = blockIdx.z;
    const int row0 = b * Lsz + c * CLEN;

    for (int i = threadIdx.x; i < CLEN * 32; i += 128) {
        int t = i >> 5, j = i & 31;
        sBC[i] = xdbl[(size_t)(row0 + t) * XDBLW + DTR + j];
    }
    __syncthreads();

    float A[NST];
    bool fast = load_A(A, A_log, d);
    float h[NST];
#pragma unroll
    for (int n = 0; n < NST; n++) h[n] = 0.f;
    float sdt = 0.f;

#pragma unroll 2
    for (int t = 0; t < CLEN; t++) {
        const int row = row0 + t;
        float dtv = __bfloat162float(dt[(size_t)row * DI + d]);
        float uv  = __bfloat162float(u [(size_t)row * DI + d]);
        float e[NST];
        compute_e(e, dtv, A, fast);
        float dtu = dtv * uv;
        sdt += dtv;
        const float* B = &sBC[t * 32];
#pragma unroll
        for (int n = 0; n < NST; n++)
            h[n] = fmaf(h[n], e[n], dtu * B[n]);
    }
    float E[NST];
    compute_e(E, sdt, A, fast);      // E = exp(A * sum dt)
    size_t base = ((size_t)(b * NC + c) * DI + d) * NST;
#pragma unroll
    for (int n = 0; n < NST; n++) { cE[base + n] = E[n]; cH[base + n] = h[n]; }
}

// ---------------- scan combine -------------------------------------------------
__global__ void scan_combine_kernel(const float* __restrict__ cE,
                                    const float* __restrict__ cH,
                                    float* __restrict__ h0out) {
    int idx = blockIdx.x * blockDim.x + threadIdx.x;
    if (idx >= Bsz * DI * NST) return;
    int b   = idx / (DI * NST);
    int rem = idx % (DI * NST);
    float h0 = 0.f;
#pragma unroll
    for (int c = 0; c < NC; c++) {
        size_t off = (size_t)(b * NC + c) * DI * NST + rem;
        h0out[off] = h0;
        h0 = fmaf(cE[off], h0, cH[off]);
    }
}

// ---------------- scan pass 2 (emits bf16 gated y) -----------------------------
__global__ __launch_bounds__(128)
void scan_pass2_kernel(const bf16* __restrict__ dt,
                       const bf16* __restrict__ u,
                       const float* __restrict__ xdbl,
                       const bf16* __restrict__ xz,
                       const float* __restrict__ A_log,
                       const float* __restrict__ Dv,
                       const float* __restrict__ h0in,
                       bf16* __restrict__ ybf) {
    __shared__ float sBC[CLEN * 32];
    const int d = blockIdx.x * 128 + threadIdx.x;
    const int c = blockIdx.y;
    const int b = blockIdx.z;
    const int row0 = b * Lsz + c * CLEN;

    for (int i = threadIdx.x; i < CLEN * 32; i += 128) {
        int t = i >> 5, j = i & 31;
        sBC[i] = xdbl[(size_t)(row0 + t) * XDBLW + DTR + j];
    }
    __syncthreads();

    float A[NST];
    bool fast = load_A(A, A_log, d);
    float h[NST];
    size_t hbase = ((size_t)(b * NC + c) * DI + d) * NST;
#pragma unroll
    for (int n = 0; n < NST; n++) h[n] = h0in[hbase + n];
    const float Dd = Dv[d];

#pragma unroll 2
    for (int t = 0; t < CLEN; t++) {
        const int row = row0 + t;
        float dtv = __bfloat162float(dt[(size_t)row * DI + d]);
        float uv  = __bfloat162float(u [(size_t)row * DI + d]);
        float zv  = __bfloat162float(xz[(size_t)row * (2 * DI) + DI + d]);
        float e[NST];
        compute_e(e, dtv, A, fast);
        float dtu = dtv * uv;
        const float* B = &sBC[t * 32];
        const float* C = &sBC[t * 32 + 16];
        float acc = 0.f;
#pragma unroll
        for (int n = 0; n < NST; n++) {
            h[n] = fmaf(h[n], e[n], dtu * B[n]);
            acc  = fmaf(h[n], C[n], acc);
        }
        float yv = fmaf(Dd, uv, acc);
        ybf[(size_t)row * DI + d] = __float2bfloat16(yv * fsilu(zv));
    }
}

// ---------------- out_proj partial sum + residual + LayerNorm ------------------
__global__ void ln_kernel(const float* __restrict__ pre,    // 2 partials stacked
                          const float* __restrict__ resid,
                          const float* __restrict__ w,
                          const float* __restrict__ bb,
                          float* __restrict__ out) {
    const int row = blockIdx.x;
    const int tid = threadIdx.x;
    __shared__ float vbuf[DM];
    __shared__ float ws[8], w2s[8];
    __shared__ float s_mu, s_inv;
    const size_t S = (size_t)MROWS * DM;
    float s = 0.f, s2 = 0.f;
    for (int i = tid; i < DM; i += blockDim.x) {
        size_t o = (size_t)row * DM + i;
        float v = pre[o] + pre[o + S] + resid[o];
        vbuf[i] = v;
        s += v; s2 += v * v;
    }
#pragma unroll
    for (int o = 16; o; o >>= 1) {
        s  += __shfl_xor_sync(0xffffffffu, s,  o);
        s2 += __shfl_xor_sync(0xffffffffu, s2, o);
    }
    int wid = tid >> 5, lane = tid & 31;
    if (lane == 0) { ws[wid] = s; w2s[wid] = s2; }
    __syncthreads();
    if (tid == 0) {
        float S1 = 0.f, S2 = 0.f;
        for (int i = 0; i < 8; i++) { S1 += ws[i]; S2 += w2s[i]; }
        float mu  = S1 / (float)DM;
        float var = S2 / (float)DM - mu * mu;
        s_mu = mu;
        s_inv = rsqrtf(var + 1e-5f);
    }
    __syncthreads();
    float mu = s_mu, inv = s_inv;
    for (int i = tid; i < DM; i += blockDim.x)
        out[(size_t)row * DM + i] = (vbuf[i] - mu) * inv * w[i] + bb[i];
}

// ---------------- launch ----------------------------------------------------
static float* sym_ptr(const void* symbol) {
    void* p = nullptr;
    cudaGetSymbolAddress(&p, symbol);
    return (float*)p;
}
static bf16* sym_ptr_bf(const void* symbol) {
    void* p = nullptr;
    cudaGetSymbolAddress(&p, symbol);
    return (bf16*)p;
}

extern "C" void kernel_launch(void* const* d_in, const int* in_sizes, int n_in,
                              void* d_out, int out_size) {
    const float* x         = (const float*)d_in[0];
    const float* in_proj_w = (const float*)d_in[1];
    const float* conv_w    = (const float*)d_in[2];
    const float* conv_b    = (const float*)d_in[3];
    const float* x_proj_w  = (const float*)d_in[4];
    const float* dt_proj_w = (const float*)d_in[5];
    const float* dt_proj_b = (const float*)d_in[6];
    const float* A_log     = (const float*)d_in[7];
    const float* Dv        = (const float*)d_in[8];
    const float* out_proj_w= (const float*)d_in[9];
    const float* ln_w      = (const float*)d_in[10];
    const float* ln_b      = (const float*)d_in[11];
    float* out = (float*)d_out;

    bf16*  xz    = sym_ptr_bf(g_xz);
    bf16*  ubf   = sym_ptr_bf(g_ubf);
    float* xdbl  = sym_ptr(g_xdbl);
    float* xpp   = sym_ptr(g_xpp);
    bf16*  dtbf  = sym_ptr_bf(g_dtbf);
    bf16*  ybf   = sym_ptr_bf(g_ybf);
    float* opp   = sym_ptr(g_opp);
    float* cE    = sym_ptr(g_cE);
    float* cH    = sym_ptr(g_cH);
    float* h0    = sym_ptr(g_h0);
    bf16* xbf    = sym_ptr_bf(g_xbf);
    bf16* xdblbf = sym_ptr_bf(g_xdblbf);
    bf16* wip    = sym_ptr_bf(g_wip);
    bf16* wxp    = sym_ptr_bf(g_wxp);
    bf16* wdt    = sym_ptr_bf(g_wdt);
    bf16* wop    = sym_ptr_bf(g_wop);

    const int M = MROWS;

    static int attr_done = 0;
    if (!attr_done) {
        cudaFuncSetAttribute(gemm_bf16_kernel<0, 1, 1>,
                             cudaFuncAttributeMaxDynamicSharedMemorySize, GSMEM);
        cudaFuncSetAttribute(gemm_bf16_kernel<0, 4, 0>,
                             cudaFuncAttributeMaxDynamicSharedMemorySize, GSMEM);
        cudaFuncSetAttribute(gemm_bf16_kernel<1, 1, 1>,
                             cudaFuncAttributeMaxDynamicSharedMemorySize, GSMEM);
        cudaFuncSetAttribute(gemm_bf16_kernel<0, 2, 0>,
                             cudaFuncAttributeMaxDynamicSharedMemorySize, GSMEM);
        attr_done = 1;
    }

    // 0a) conversions needed by in_proj (launches 1-3)
    f2bf_kernel<<<(M * DM / 2 + 255) / 256, 256>>>(x, xbf, M * DM / 2);
    f2bf_kernel<<<(2 * DI * DM / 2 + 255) / 256, 256>>>(in_proj_w, wip, 2 * DI * DM / 2);
    f2bf_kernel<<<(XDBLW * DI / 2 + 255) / 256, 256>>>(x_proj_w, wxp, XDBLW * DI / 2);

    // 1) in_proj: xz[M, 3072] = x @ in_proj_w^T  (bf16 out)  [launch #4 -> profiled]
    gemm_bf16_kernel<0, 1, 1><<<dim3((2 * DI) / 128, M / 128, 1), 256, GSMEM>>>(
        xbf, DM, wip, DM, nullptr, xz, M, 2 * DI, DM);

    // 0b) remaining conversions (independent of in_proj output)
    f2bf_kernel<<<(DM * DI / 2 + 255) / 256, 256>>>(out_proj_w, wop, DM * DI / 2);
    dtw_pad_kernel<<<(DI * KDT + 255) / 256, 256>>>(dt_proj_w, wdt);

    // 2) causal depthwise conv + SiLU -> ubf
    conv_silu_kernel<<<(M * DI / 8 + 255) / 256, 256>>>(xz, conv_w, conv_b, ubf);

    // 3) x_proj: xdbl[M, 80] = u @ x_proj_w^T (split-K = 4, fp32 partials)
    gemm_bf16_kernel<0, 4, 0><<<dim3(1, M / 128, 4), 256, GSMEM>>>(
        ubf, DI, wxp, DI, nullptr, xpp, M, XDBLW, DI);
    xp_reduce_kernel<<<(M * XDBLW + 255) / 256, 256>>>(xpp, xdbl, xdblbf);

    // 4) dt[M,1536] = softplus(dtl @ dt_proj_w^T + b)  (bf16 out; K padded 48->64)
    gemm_bf16_kernel<1, 1, 1><<<dim3(DI / 128, M / 128, 1), 256, GSMEM>>>(
        xdblbf, XDBLW, wdt, KDT, dt_proj_b, dtbf, M, DI, KDT);

    // 5) chunk-parallel selective scan + gate -> ybf
    scan_pass1_kernel<<<dim3(DI / 128, NC, Bsz), 128>>>(dtbf, ubf, xdbl, A_log, cE, cH);
    scan_combine_kernel<<<(Bsz * DI * NST + 255) / 256, 256>>>(cE, cH, h0);
    scan_pass2_kernel<<<dim3(DI / 128, NC, Bsz), 128>>>(dtbf, ubf, xdbl, xz, A_log, Dv, h0, ybf);

    // 6) out_proj: opp[z][M,768] = y @ out_proj_w^T (split-K = 2)
    gemm_bf16_kernel<0, 2, 0><<<dim3(DM / 128, M / 128, 2), 256, GSMEM>>>(
        ybf, DI, wop, DI, nullptr, opp, M, DM, DI);

    // 7) partial-sum + residual + LayerNorm -> d_out
    ln_kernel<<<M, 256>>>(opp, x, ln_w, ln_b, out);
}

// round 12
// speedup vs baseline: 1.4365x; 1.3551x over previous
#include <cuda_runtime.h>
#include <cuda_bf16.h>
#include <math.h>
#include <stdint.h>

#define Bsz   2
#define Lsz   2048
#define DM    768
#define DI    1536
#define NST   16
#define DTR   48
#define XDBLW 80          // DTR + 2*NST
#define MROWS (Bsz*Lsz)   // 4096
#define NC    32          // scan chunks
#define CLEN  (Lsz/NC)    // 64
#define KDT   64          // padded K for dt GEMM

typedef __nv_bfloat16 bf16;

// ---------------- scratch (device globals; no allocs allowed) ----------------
__device__ bf16  g_xz  [MROWS * 2 * DI];       // in_proj output: u_raw | z (bf16)
__device__ bf16  g_ubf [MROWS * DI];           // post conv+silu (bf16)
__device__ float g_xdbl[MROWS * XDBLW];        // dtl | B | C (fp32, scan B/C)
__device__ float g_xpp [4 * MROWS * XDBLW];    // x_proj split-K partials
__device__ bf16  g_dtbf[MROWS * DI];           // softplus(dt) (bf16)
__device__ bf16  g_ybf [MROWS * DI];           // gated scan output (bf16)
__device__ float g_opp [2 * MROWS * DM];       // out_proj split-K partials
__device__ float g_cE  [Bsz * NC * DI * NST];
__device__ float g_cH  [Bsz * NC * DI * NST];
__device__ float g_h0  [Bsz * NC * DI * NST];
// bf16 mirrors for tensor-core GEMM operands
__device__ bf16 g_xbf   [MROWS * DM];          // x
__device__ bf16 g_xdblbf[MROWS * XDBLW];       // xdbl
__device__ bf16 g_wip   [2 * DI * DM];         // in_proj_w
__device__ bf16 g_wxp   [XDBLW * DI];          // x_proj_w
__device__ bf16 g_wdt   [DI * KDT];            // dt_proj_w zero-padded 48->64
__device__ bf16 g_wop   [DM * DI];             // out_proj_w

// ---------------- helpers ----------------------------------------------------
__device__ __forceinline__ void mma_bf16(float* c, const uint32_t* a, const uint32_t* b) {
    asm volatile(
        "mma.sync.aligned.m16n8k16.row.col.f32.bf16.bf16.f32 "
        "{%0,%1,%2,%3}, {%4,%5,%6,%7}, {%8,%9}, {%0,%1,%2,%3};\n"
        : "+f"(c[0]), "+f"(c[1]), "+f"(c[2]), "+f"(c[3])
        : "r"(a[0]), "r"(a[1]), "r"(a[2]), "r"(a[3]), "r"(b[0]), "r"(b[1]));
}

__device__ __forceinline__ void ldsm4(uint32_t* r, uint32_t addr) {
    asm volatile("ldmatrix.sync.aligned.m8n8.x4.shared.b16 {%0,%1,%2,%3}, [%4];"
                 : "=r"(r[0]), "=r"(r[1]), "=r"(r[2]), "=r"(r[3]) : "r"(addr));
}

__device__ __forceinline__ float fsilu(float x) {
    return x * __fdividef(1.f, 1.f + __expf(-x));
}

__device__ __forceinline__ void cp16u(uint32_t sdst, const void* gsrc, bool pred) {
    int sz = pred ? 16 : 0;                       // src-size 0 -> zero-fill
    asm volatile("cp.async.cg.shared.global [%0], [%1], 16, %2;\n"
                 :: "r"(sdst), "l"(gsrc), "r"(sz));
}
__device__ __forceinline__ void cp_commit() { asm volatile("cp.async.commit_group;\n"); }
template<int N_>
__device__ __forceinline__ void cp_wait() { asm volatile("cp.async.wait_group %0;\n" :: "n"(N_)); }

// ---------------- fused fp32 -> bf16 conversion (all weights + x) -------------
__device__ __forceinline__ void cvt2(const float* __restrict__ s, bf16* __restrict__ d, int i) {
    float2 v = ((const float2*)s)[i];
    ((__nv_bfloat162*)d)[i] = __float22bfloat162_rn(v);
}

#define CN0 (MROWS * DM / 2)              // x
#define CN1 (CN0 + DI * DM)               // + in_proj_w (2*DI*DM/2)
#define CN2 (CN1 + XDBLW * DI / 2)        // + x_proj_w
#define CN3 (CN2 + DM * DI / 2)           // + out_proj_w
#define CN4 (CN3 + DI * 32)               // + dt pad units (DI*KDT/2)

__global__ void convert_all_kernel(const float* __restrict__ x,
                                   const float* __restrict__ wip_f,
                                   const float* __restrict__ wxp_f,
                                   const float* __restrict__ wop_f,
                                   const float* __restrict__ wdt_f,
                                   bf16* __restrict__ xbf, bf16* __restrict__ wip,
                                   bf16* __restrict__ wxp, bf16* __restrict__ wop,
                                   bf16* __restrict__ wdt) {
    int i = blockIdx.x * blockDim.x + threadIdx.x;
    if (i < CN0)      cvt2(x, xbf, i);
    else if (i < CN1) cvt2(wip_f, wip, i - CN0);
    else if (i < CN2) cvt2(wxp_f, wxp, i - CN1);
    else if (i < CN3) cvt2(wop_f, wop, i - CN2);
    else if (i < CN4) {
        int j = i - CN3;                  // unit over DI x 32 (pairs of cols)
        int r = j >> 5, c2 = j & 31;
        float v0 = 0.f, v1 = 0.f;
        if (c2 < 24) { v0 = wdt_f[r * DTR + 2 * c2]; v1 = wdt_f[r * DTR + 2 * c2 + 1]; }
        ((__nv_bfloat162*)wdt)[r * 32 + c2] = __float22bfloat162_rn(make_float2(v0, v1));
    }
}

// ---------------- pipelined bf16 HMMA GEMM (ldmatrix, BK=64, 3-stage) ---------
// C[M,N] = A[M,K(lda)] * W[N,K(ldw)]^T, bf16 in, fp32 accum.
// CTA tile 128x128, BK=64, 3-stage cp.async ring, ldmatrix fragment loads.
// 2 CTAs/SM (221KB smem of 227KB).
// OBF==1: bf16 out; SPLITK via blockIdx.z (fp32 partials); EPI==1: softplus+bias.
#define SPB   72                 // smem row pitch in bf16 (64 data + 8 pad)
#define NSTG  3
#define ASTG  (128 * SPB * 2)    // 18432 bytes per stage per array
#define GSMEM (2 * NSTG * ASTG)  // 110592 bytes total

template<int EPI, int SPLITK, int OBF>
__global__ __launch_bounds__(256, 2)
void gemm_bf16_kernel(const bf16* __restrict__ A, int lda,
                      const bf16* __restrict__ W, int ldw,
                      const float* __restrict__ bias,
                      void* __restrict__ Cv,
                      int M, int N, int K) {
    extern __shared__ char dsm[];
    const uint32_t smemu = (uint32_t)__cvta_generic_to_shared(dsm);
    const int tx   = threadIdx.x;
    const int lane = tx & 31;
    const int wid  = tx >> 5;
    const int warp_m = wid & 3;
    const int warp_n = wid >> 2;
    const int brow = blockIdx.y * 128;
    const int bcol = blockIdx.x * 128;
    const int q = lane & 3;
    const int g = lane >> 2;

    const int kn = K / SPLITK;
    const int kBegin = blockIdx.z * kn;
    const int KT = kn / 64;

    // staging: 1024 x 16B chunks per array-stage; 4 per thread
    int rS[4], eS[4];
#pragma unroll
    for (int i = 0; i < 4; i++) {
        int c = tx + i * 256;
        rS[i] = c >> 3;
        eS[i] = (c & 7) << 3;
    }

    // ldmatrix per-lane byte offsets (kk=0) within a stage buffer
    uint32_t offA[2];
#pragma unroll
    for (int i = 0; i < 2; i++)
        offA[i] = (uint32_t)(((warp_m * 32 + i * 16 + (lane & 15)) * SPB
                              + ((lane >> 4) << 3)) * 2);
    uint32_t offB[4];
#pragma unroll
    for (int jj = 0; jj < 4; jj++)
        offB[jj] = (uint32_t)(((warp_n * 64 + jj * 16 + (lane & 7) + ((lane >> 4) << 3)) * SPB
                               + (((lane >> 3) & 1) << 3)) * 2);

    float acc[2][8][4];
#pragma unroll
    for (int i = 0; i < 2; i++)
#pragma unroll
        for (int j = 0; j < 8; j++)
#pragma unroll
            for (int v = 0; v < 4; v++) acc[i][j][v] = 0.f;

    auto stage = [&](int kt) {
        int st = kt % NSTG;
        uint32_t ab = smemu + st * ASTG;
        uint32_t bb = smemu + NSTG * ASTG + st * ASTG;
        int k0 = kBegin + kt * 64;
#pragma unroll
        for (int i = 0; i < 4; i++) {
            cp16u(ab + (uint32_t)((rS[i] * SPB + eS[i]) * 2),
                  A + (size_t)(brow + rS[i]) * lda + k0 + eS[i], true);
            cp16u(bb + (uint32_t)((rS[i] * SPB + eS[i]) * 2),
                  W + (size_t)(bcol + rS[i]) * ldw + k0 + eS[i], (bcol + rS[i]) < N);
        }
        cp_commit();
    };

#pragma unroll
    for (int s = 0; s < NSTG; s++) {
        if (s < KT) stage(s); else cp_commit();
    }

    for (int kt = 0; kt < KT; kt++) {
        cp_wait<NSTG - 1>();
        __syncthreads();
        const int st = kt % NSTG;
        const uint32_t ab = smemu + st * ASTG;
        const uint32_t bb = smemu + NSTG * ASTG + st * ASTG;
#pragma unroll
        for (int kk = 0; kk < 64; kk += 16) {
            uint32_t af[2][4], bfr[4][4];
            ldsm4(af[0], ab + offA[0] + kk * 2);
            ldsm4(af[1], ab + offA[1] + kk * 2);
#pragma unroll
            for (int jj = 0; jj < 4; jj++)
                ldsm4(bfr[jj], bb + offB[jj] + kk * 2);
#pragma unroll
            for (int i = 0; i < 2; i++)
#pragma unroll
                for (int j = 0; j < 8; j++) {
                    const uint32_t* bp = &bfr[j >> 1][(j & 1) << 1];
                    mma_bf16(acc[i][j], af[i], bp);
                }
        }
        __syncthreads();
        if (kt + NSTG < KT) stage(kt + NSTG); else cp_commit();
    }

    // epilogue
    float* Cf = (float*)Cv + (size_t)blockIdx.z * M * N;
    bf16*  Cb = (bf16*)Cv;
#pragma unroll
    for (int i = 0; i < 2; i++) {
#pragma unroll
        for (int j = 0; j < 8; j++) {
            int r0w = brow + warp_m * 32 + i * 16 + g;
            int c0w = bcol + warp_n * 64 + j * 8 + 2 * q;
            if (c0w >= N) continue;
            float v0 = acc[i][j][0], v1 = acc[i][j][1];
            float v2 = acc[i][j][2], v3 = acc[i][j][3];
            if (EPI == 1) {
                float b0 = bias[c0w], b1 = bias[c0w + 1];
                v0 += b0; v1 += b1; v2 += b0; v3 += b1;
                v0 = (v0 > 15.f) ? v0 : __logf(1.f + __expf(v0));
                v1 = (v1 > 15.f) ? v1 : __logf(1.f + __expf(v1));
                v2 = (v2 > 15.f) ? v2 : __logf(1.f + __expf(v2));
                v3 = (v3 > 15.f) ? v3 : __logf(1.f + __expf(v3));
            }
            if (OBF) {
                *(__nv_bfloat162*)(Cb + (size_t)r0w * N + c0w) =
                    __float22bfloat162_rn(make_float2(v0, v1));
                *(__nv_bfloat162*)(Cb + (size_t)(r0w + 8) * N + c0w) =
                    __float22bfloat162_rn(make_float2(v2, v3));
            } else {
                *(float2*)(Cf + (size_t)r0w * N + c0w)       = make_float2(v0, v1);
                *(float2*)(Cf + (size_t)(r0w + 8) * N + c0w) = make_float2(v2, v3);
            }
        }
    }
}

// ---------------- x_proj split-K reduce (fp32 + bf16 outputs) ----------------
__global__ void xp_reduce_kernel(const float* __restrict__ p,
                                 float* __restrict__ o,
                                 bf16* __restrict__ obf) {
    int i = blockIdx.x * blockDim.x + threadIdx.x;
    const int S = MROWS * XDBLW;
    if (i >= S) return;
    float v = (p[i] + p[i + S]) + (p[i + 2 * S] + p[i + 3 * S]);
    o[i] = v;
    obf[i] = __float2bfloat16(v);
}

// ---------------- causal depthwise conv (k=4) + bias + SiLU ------------------
// Thread owns one channel d and 8 consecutive l's: weights loaded ONCE
// (1 float4/thread), xz loads coalesced per-l across the warp (32 consecutive d).
__global__ __launch_bounds__(256)
void conv_silu_kernel(const bf16* __restrict__ xz,
                      const float* __restrict__ cw,
                      const float* __restrict__ cb,
                      bf16* __restrict__ u) {
    const int lane = threadIdx.x & 31;
    const int w    = threadIdx.x >> 5;
    const int d  = blockIdx.x * 32 + lane;       // blockIdx.x in [0, DI/32)
    const int l0 = (blockIdx.y * 8 + w) * 8;     // blockIdx.y in [0, Lsz/64)
    const int b  = blockIdx.z;

    float4 wk = ((const float4*)cw)[d];
    float bias = cb[d];

    float xv[11];
#pragma unroll
    for (int i = 0; i < 11; i++) {
        int ls = l0 - 3 + i;
        xv[i] = (ls >= 0)
            ? __bfloat162float(xz[(size_t)(b * Lsz + ls) * (2 * DI) + d]) : 0.f;
    }
#pragma unroll
    for (int j = 0; j < 8; j++) {
        float acc = bias;
        acc = fmaf(wk.x, xv[j],     acc);
        acc = fmaf(wk.y, xv[j + 1], acc);
        acc = fmaf(wk.z, xv[j + 2], acc);
        acc = fmaf(wk.w, xv[j + 3], acc);
        u[(size_t)(b * Lsz + l0 + j) * DI + d] = __float2bfloat16(fsilu(acc));
    }
}

// ---------------- scan: shared pieces ----------------------------------------
__device__ __forceinline__ void compute_e(float e[NST], float dtv,
                                          const float A[NST], bool fast) {
    if (fast) {
        float p  = __expf(-dtv);
        float p2 = p * p, p4 = p2 * p2, p8 = p4 * p4;
        e[0]  = p;        e[1]  = p2;       e[2]  = p2 * p;   e[3]  = p4;
        e[4]  = p4 * p;   e[5]  = p4 * p2;  e[6]  = p4 * e[2];e[7]  = p8;
        e[8]  = p8 * p;   e[9]  = p8 * p2;  e[10] = p8 * e[2];e[11] = p8 * p4;
        e[12] = p8 * e[4];e[13] = p8 * e[5];e[14] = p8 * e[6];e[15] = p8 * p8;
    } else {
#pragma unroll
        for (int n = 0; n < NST; n++) e[n] = __expf(dtv * A[n]);
    }
}

__device__ __forceinline__ bool load_A(float A[NST], const float* __restrict__ A_log, int d) {
    bool fast = true;
#pragma unroll
    for (int n = 0; n < NST; n++) {
        A[n] = -expf(A_log[d * NST + n]);
        fast = fast && (fabsf(A[n] + (float)(n + 1)) <= 1e-3f * (float)(n + 1));
    }
    return fast;
}

// ---------------- scan pass 1 --------------------------------------------------
// E[n] = exp(A[n] * sum_t dt_t): accumulate one scalar, expand at chunk end.
__global__ __launch_bounds__(128)
void scan_pass1_kernel(const bf16* __restrict__ dt,
                       const bf16* __restrict__ u,
                       const float* __restrict__ xdbl,
                       const float* __restrict__ A_log,
                       float* __restrict__ cE,
                       float* __restrict__ cH) {
    __shared__ float sBC[CLEN * 32];
    const int d = blockIdx.x * 128 + threadIdx.x;
    const int c = blockIdx.y;
    const int b = blockIdx.z;
    const int row0 = b * Lsz + c * CLEN;

    for (int i = threadIdx.x; i < CLEN * 32; i += 128) {
        int t = i >> 5, j = i & 31;
        sBC[i] = xdbl[(size_t)(row0 + t) * XDBLW + DTR + j];
    }
    __syncthreads();

    float A[NST];
    bool fast = load_A(A, A_log, d);
    float h[NST];
#pragma unroll
    for (int n = 0; n < NST; n++) h[n] = 0.f;
    float sdt = 0.f;

#pragma unroll 2
    for (int t = 0; t < CLEN; t++) {
        const int row = row0 + t;
        float dtv = __bfloat162float(dt[(size_t)row * DI + d]);
        float uv  = __bfloat162float(u [(size_t)row * DI + d]);
        float e[NST];
        compute_e(e, dtv, A, fast);
        float dtu = dtv * uv;
        sdt += dtv;
        const float* B = &sBC[t * 32];
#pragma unroll
        for (int n = 0; n < NST; n++)
            h[n] = fmaf(h[n], e[n], dtu * B[n]);
    }
    float E[NST];
    compute_e(E, sdt, A, fast);      // E = exp(A * sum dt)
    size_t base = ((size_t)(b * NC + c) * DI + d) * NST;
#pragma unroll
    for (int n = 0; n < NST; n++) { cE[base + n] = E[n]; cH[base + n] = h[n]; }
}

// ---------------- scan combine -------------------------------------------------
__global__ void scan_combine_kernel(const float* __restrict__ cE,
                                    const float* __restrict__ cH,
                                    float* __restrict__ h0out) {
    int idx = blockIdx.x * blockDim.x + threadIdx.x;
    if (idx >= Bsz * DI * NST) return;
    int b   = idx / (DI * NST);
    int rem = idx % (DI * NST);
    float h0 = 0.f;
#pragma unroll
    for (int c = 0; c < NC; c++) {
        size_t off = (size_t)(b * NC + c) * DI * NST + rem;
        h0out[off] = h0;
        h0 = fmaf(cE[off], h0, cH[off]);
    }
}

// ---------------- scan pass 2 (emits bf16 gated y) -----------------------------
__global__ __launch_bounds__(128)
void scan_pass2_kernel(const bf16* __restrict__ dt,
                       const bf16* __restrict__ u,
                       const float* __restrict__ xdbl,
                       const bf16* __restrict__ xz,
                       const float* __restrict__ A_log,
                       const float* __restrict__ Dv,
                       const float* __restrict__ h0in,
                       bf16* __restrict__ ybf) {
    __shared__ float sBC[CLEN * 32];
    const int d = blockIdx.x * 128 + threadIdx.x;
    const int c = blockIdx.y;
    const int b = blockIdx.z;
    const int row0 = b * Lsz + c * CLEN;

    for (int i = threadIdx.x; i < CLEN * 32; i += 128) {
        int t = i >> 5, j = i & 31;
        sBC[i] = xdbl[(size_t)(row0 + t) * XDBLW + DTR + j];
    }
    __syncthreads();

    float A[NST];
    bool fast = load_A(A, A_log, d);
    float h[NST];
    size_t hbase = ((size_t)(b * NC + c) * DI + d) * NST;
#pragma unroll
    for (int n = 0; n < NST; n++) h[n] = h0in[hbase + n];
    const float Dd = Dv[d];

#pragma unroll 2
    for (int t = 0; t < CLEN; t++) {
        const int row = row0 + t;
        float dtv = __bfloat162float(dt[(size_t)row * DI + d]);
        float uv  = __bfloat162float(u [(size_t)row * DI + d]);
        float zv  = __bfloat162float(xz[(size_t)row * (2 * DI) + DI + d]);
        float e[NST];
        compute_e(e, dtv, A, fast);
        float dtu = dtv * uv;
        const float* B = &sBC[t * 32];
        const float* C = &sBC[t * 32 + 16];
        float acc = 0.f;
#pragma unroll
        for (int n = 0; n < NST; n++) {
            h[n] = fmaf(h[n], e[n], dtu * B[n]);
            acc  = fmaf(h[n], C[n], acc);
        }
        float yv = fmaf(Dd, uv, acc);
        ybf[(size_t)row * DI + d] = __float2bfloat16(yv * fsilu(zv));
    }
}

// ---------------- out_proj partial sum + residual + LayerNorm ------------------
__global__ void ln_kernel(const float* __restrict__ pre,    // 2 partials stacked
                          const float* __restrict__ resid,
                          const float* __restrict__ w,
                          const float* __restrict__ bb,
                          float* __restrict__ out) {
    const int row = blockIdx.x;
    const int tid = threadIdx.x;
    __shared__ float vbuf[DM];
    __shared__ float ws[8], w2s[8];
    __shared__ float s_mu, s_inv;
    const size_t S = (size_t)MROWS * DM;
    float s = 0.f, s2 = 0.f;
    for (int i = tid; i < DM; i += blockDim.x) {
        size_t o = (size_t)row * DM + i;
        float v = pre[o] + pre[o + S] + resid[o];
        vbuf[i] = v;
        s += v; s2 += v * v;
    }
#pragma unroll
    for (int o = 16; o; o >>= 1) {
        s  += __shfl_xor_sync(0xffffffffu, s,  o);
        s2 += __shfl_xor_sync(0xffffffffu, s2, o);
    }
    int wid = tid >> 5, lane = tid & 31;
    if (lane == 0) { ws[wid] = s; w2s[wid] = s2; }
    __syncthreads();
    if (tid == 0) {
        float S1 = 0.f, S2 = 0.f;
        for (int i = 0; i < 8; i++) { S1 += ws[i]; S2 += w2s[i]; }
        float mu  = S1 / (float)DM;
        float var = S2 / (float)DM - mu * mu;
        s_mu = mu;
        s_inv = rsqrtf(var + 1e-5f);
    }
    __syncthreads();
    float mu = s_mu, inv = s_inv;
    for (int i = tid; i < DM; i += blockDim.x)
        out[(size_t)row * DM + i] = (vbuf[i] - mu) * inv * w[i] + bb[i];
}

// ---------------- launch ----------------------------------------------------
static float* sym_ptr(const void* symbol) {
    void* p = nullptr;
    cudaGetSymbolAddress(&p, symbol);
    return (float*)p;
}
static bf16* sym_ptr_bf(const void* symbol) {
    void* p = nullptr;
    cudaGetSymbolAddress(&p, symbol);
    return (bf16*)p;
}

extern "C" void kernel_launch(void* const* d_in, const int* in_sizes, int n_in,
                              void* d_out, int out_size) {
    const float* x         = (const float*)d_in[0];
    const float* in_proj_w = (const float*)d_in[1];
    const float* conv_w    = (const float*)d_in[2];
    const float* conv_b    = (const float*)d_in[3];
    const float* x_proj_w  = (const float*)d_in[4];
    const float* dt_proj_w = (const float*)d_in[5];
    const float* dt_proj_b = (const float*)d_in[6];
    const float* A_log     = (const float*)d_in[7];
    const float* Dv        = (const float*)d_in[8];
    const float* out_proj_w= (const float*)d_in[9];
    const float* ln_w      = (const float*)d_in[10];
    const float* ln_b      = (const float*)d_in[11];
    float* out = (float*)d_out;

    bf16*  xz    = sym_ptr_bf(g_xz);
    bf16*  ubf   = sym_ptr_bf(g_ubf);
    float* xdbl  = sym_ptr(g_xdbl);
    float* xpp   = sym_ptr(g_xpp);
    bf16*  dtbf  = sym_ptr_bf(g_dtbf);
    bf16*  ybf   = sym_ptr_bf(g_ybf);
    float* opp   = sym_ptr(g_opp);
    float* cE    = sym_ptr(g_cE);
    float* cH    = sym_ptr(g_cH);
    float* h0    = sym_ptr(g_h0);
    bf16* xbf    = sym_ptr_bf(g_xbf);
    bf16* xdblbf = sym_ptr_bf(g_xdblbf);
    bf16* wip    = sym_ptr_bf(g_wip);
    bf16* wxp    = sym_ptr_bf(g_wxp);
    bf16* wdt    = sym_ptr_bf(g_wdt);
    bf16* wop    = sym_ptr_bf(g_wop);

    const int M = MROWS;

    static int attr_done = 0;
    if (!attr_done) {
        cudaFuncSetAttribute(gemm_bf16_kernel<0, 1, 1>,
                             cudaFuncAttributeMaxDynamicSharedMemorySize, GSMEM);
        cudaFuncSetAttribute(gemm_bf16_kernel<0, 4, 0>,
                             cudaFuncAttributeMaxDynamicSharedMemorySize, GSMEM);
        cudaFuncSetAttribute(gemm_bf16_kernel<1, 1, 1>,
                             cudaFuncAttributeMaxDynamicSharedMemorySize, GSMEM);
        cudaFuncSetAttribute(gemm_bf16_kernel<0, 2, 0>,
                             cudaFuncAttributeMaxDynamicSharedMemorySize, GSMEM);
        attr_done = 1;
    }

    // 0) all fp32 -> bf16 conversions in ONE kernel
    convert_all_kernel<<<(CN4 + 255) / 256, 256>>>(
        x, in_proj_w, x_proj_w, out_proj_w, dt_proj_w,
        xbf, wip, wxp, wop, wdt);

    // 1) in_proj: xz[M, 3072] = x @ in_proj_w^T  (bf16 out)
    gemm_bf16_kernel<0, 1, 1><<<dim3((2 * DI) / 128, M / 128, 1), 256, GSMEM>>>(
        xbf, DM, wip, DM, nullptr, xz, M, 2 * DI, DM);

    // 2) causal depthwise conv + SiLU -> ubf
    conv_silu_kernel<<<dim3(DI / 32, Lsz / 64, Bsz), 256>>>(xz, conv_w, conv_b, ubf);

    // 3) x_proj: xdbl[M, 80] = u @ x_proj_w^T (split-K = 4, fp32 partials)
    gemm_bf16_kernel<0, 4, 0><<<dim3(1, M / 128, 4), 256, GSMEM>>>(
        ubf, DI, wxp, DI, nullptr, xpp, M, XDBLW, DI);
    xp_reduce_kernel<<<(M * XDBLW + 255) / 256, 256>>>(xpp, xdbl, xdblbf);

    // 4) dt[M,1536] = softplus(dtl @ dt_proj_w^T + b)  (bf16 out; K padded 48->64)
    gemm_bf16_kernel<1, 1, 1><<<dim3(DI / 128, M / 128, 1), 256, GSMEM>>>(
        xdblbf, XDBLW, wdt, KDT, dt_proj_b, dtbf, M, DI, KDT);

    // 5) chunk-parallel selective scan + gate -> ybf
    scan_pass1_kernel<<<dim3(DI / 128, NC, Bsz), 128>>>(dtbf, ubf, xdbl, A_log, cE, cH);
    scan_combine_kernel<<<(Bsz * DI * NST + 255) / 256, 256>>>(cE, cH, h0);
    scan_pass2_kernel<<<dim3(DI / 128, NC, Bsz), 128>>>(dtbf, ubf, xdbl, xz, A_log, Dv, h0, ybf);

    // 6) out_proj: opp[z][M,768] = y @ out_proj_w^T (split-K = 2)
    gemm_bf16_kernel<0, 2, 0><<<dim3(DM / 128, M / 128, 2), 256, GSMEM>>>(
        ybf, DI, wop, DI, nullptr, opp, M, DM, DI);

    // 7) partial-sum + residual + LayerNorm -> d_out
    ln_kernel<<<M, 256>>>(opp, x, ln_w, ln_b, out);
}